// round 1
// baseline (speedup 1.0000x reference)
#include <cuda_runtime.h>
#include <math.h>

// ---------------------------------------------------------------------------
// Problem constants
//   x:      (B=2, S=2048, EMB=2048)
//   q_a_w:  (1536, 2048)   q_b_w: (2048, 1536)
//   kv_a_w: (576, 2048)    kv_b_w: (3072, 512)
//   o_w:    (2048, 2048)
// ---------------------------------------------------------------------------
#define BATCH   2
#define SLEN    2048
#define EMB     2048
#define NHEAD   16
#define QRANK   1536
#define KVRANK  512
#define ROPE_D  64
#define QK_D    128
#define V_D     128
#define MROWS   (BATCH * SLEN)        // 4096

// ------------------------- device scratch (no allocs) ---------------------
__device__ float g_Xq [(size_t)MROWS * QRANK];          // 4096 x 1536
__device__ float g_Q  [(size_t)MROWS * (NHEAD * QK_D)]; // 4096 x 2048 (pre-rope)
__device__ float g_CKV[(size_t)MROWS * 576];            // 4096 x 576
__device__ float g_KVB[(size_t)MROWS * 3072];           // 4096 x 3072
__device__ float g_Qb [(size_t)BATCH * NHEAD * SLEN * QK_D]; // [BH][S][128]
__device__ float g_Kb [(size_t)BATCH * NHEAD * SLEN * QK_D];
__device__ float g_Vb [(size_t)BATCH * NHEAD * SLEN * V_D];
__device__ float g_O  [(size_t)MROWS * (NHEAD * V_D)];  // 4096 x 2048

// ---------------------------------------------------------------------------
// Generic SGEMM (NT): C[M,N] = A[M,K] @ B[N,K]^T
// 128x128 tile, TK=16, 256 threads, 8x8 per thread.
// M must be a multiple of 128 (always 4096 here). N guarded (576 case).
// ---------------------------------------------------------------------------
__global__ __launch_bounds__(256, 2)
void sgemm_nt(const float* __restrict__ A, const float* __restrict__ B,
              float* __restrict__ C, int M, int N, int K,
              int lda, int ldb, int ldc)
{
    __shared__ float As[16][132];
    __shared__ float Bs[16][132];

    const int tid = threadIdx.x;
    const int tx  = tid & 15;
    const int ty  = tid >> 4;
    const int bm  = blockIdx.y * 128;
    const int bn  = blockIdx.x * 128;

    const int lrow = tid >> 2;         // 0..63
    const int lcol = (tid & 3) << 2;   // 0,4,8,12

    float acc[8][8];
    #pragma unroll
    for (int i = 0; i < 8; ++i)
        #pragma unroll
        for (int j = 0; j < 8; ++j) acc[i][j] = 0.f;

    for (int k0 = 0; k0 < K; k0 += 16) {
        #pragma unroll
        for (int rr = 0; rr < 2; ++rr) {
            const int row = lrow + rr * 64;
            float4 av = *(const float4*)(A + (size_t)(bm + row) * lda + k0 + lcol);
            As[lcol + 0][row] = av.x;
            As[lcol + 1][row] = av.y;
            As[lcol + 2][row] = av.z;
            As[lcol + 3][row] = av.w;
            float4 bv = make_float4(0.f, 0.f, 0.f, 0.f);
            if (bn + row < N)
                bv = *(const float4*)(B + (size_t)(bn + row) * ldb + k0 + lcol);
            Bs[lcol + 0][row] = bv.x;
            Bs[lcol + 1][row] = bv.y;
            Bs[lcol + 2][row] = bv.z;
            Bs[lcol + 3][row] = bv.w;
        }
        __syncthreads();

        #pragma unroll
        for (int kk = 0; kk < 16; ++kk) {
            float a[8], bq[8];
            *(float4*)&a[0]  = *(const float4*)&As[kk][ty * 4];
            *(float4*)&a[4]  = *(const float4*)&As[kk][64 + ty * 4];
            *(float4*)&bq[0] = *(const float4*)&Bs[kk][tx * 4];
            *(float4*)&bq[4] = *(const float4*)&Bs[kk][64 + tx * 4];
            #pragma unroll
            for (int i = 0; i < 8; ++i)
                #pragma unroll
                for (int j = 0; j < 8; ++j)
                    acc[i][j] = fmaf(a[i], bq[j], acc[i][j]);
        }
        __syncthreads();
    }

    #pragma unroll
    for (int i = 0; i < 8; ++i) {
        const int row = bm + ((i < 4) ? (ty * 4 + i) : (64 + ty * 4 + i - 4));
        {
            const int col = bn + tx * 4;
            if (col < N) {
                float4 v = make_float4(acc[i][0], acc[i][1], acc[i][2], acc[i][3]);
                *(float4*)(C + (size_t)row * ldc + col) = v;
            }
        }
        {
            const int col = bn + 64 + tx * 4;
            if (col < N) {
                float4 v = make_float4(acc[i][4], acc[i][5], acc[i][6], acc[i][7]);
                *(float4*)(C + (size_t)row * ldc + col) = v;
            }
        }
    }
}

// ---------------------------------------------------------------------------
// Repack Q:  g_Q [bs][h*128 + d]  ->  g_Qb [(b*16+h)*2048 + s][d]
// with interleaved RoPE applied to dims [64,128).
// block (64,16), grid MROWS
// ---------------------------------------------------------------------------
__global__ void build_q(const float* __restrict__ Q, float* __restrict__ Qb)
{
    const int bs = blockIdx.x;
    const int b  = bs >> 11;          // / 2048
    const int s  = bs & 2047;
    const int h  = threadIdx.y;
    const int t  = threadIdx.x;       // 0..63

    const float* src = Q + (size_t)bs * (NHEAD * QK_D) + h * QK_D;
    float* dst = Qb + ((size_t)(b * NHEAD + h) * SLEN + s) * QK_D;

    dst[t] = src[t];                  // q_pass

    if (t < 32) {
        const float theta = powf(10000.f, -((float)(2 * t)) / 64.f);
        float sn, cs;
        sincosf((float)s * theta, &sn, &cs);
        const float x0 = src[64 + 2 * t];
        const float x1 = src[64 + 2 * t + 1];
        dst[64 + 2 * t]     = x0 * cs - x1 * sn;
        dst[64 + 2 * t + 1] = x1 * cs + x0 * sn;
    }
}

// ---------------------------------------------------------------------------
// Repack K,V:
//   K[(b,h,s)][0:64]   = KVB[bs][h*192 + 0:64]
//   K[(b,h,s)][64:128] = rope(CKV[bs][512:576], pos=s)   (shared across heads)
//   V[(b,h,s)][0:128]  = KVB[bs][h*192 + 64:192]
// ---------------------------------------------------------------------------
__global__ void build_kv(const float* __restrict__ KVB, const float* __restrict__ CKV,
                         float* __restrict__ Kb, float* __restrict__ Vb)
{
    const int bs = blockIdx.x;
    const int b  = bs >> 11;
    const int s  = bs & 2047;
    const int h  = threadIdx.y;
    const int t  = threadIdx.x;       // 0..63

    const float* kv = KVB + (size_t)bs * 3072 + h * 192;
    float* dk = Kb + ((size_t)(b * NHEAD + h) * SLEN + s) * QK_D;
    float* dv = Vb + ((size_t)(b * NHEAD + h) * SLEN + s) * V_D;

    dk[t]      = kv[t];          // k_pass
    dv[t]      = kv[64 + t];     // v[0:64]
    dv[64 + t] = kv[128 + t];    // v[64:128]

    if (t < 32) {
        const float theta = powf(10000.f, -((float)(2 * t)) / 64.f);
        float sn, cs;
        sincosf((float)s * theta, &sn, &cs);
        const float* kr = CKV + (size_t)bs * 576 + 512;
        const float x0 = kr[2 * t];
        const float x1 = kr[2 * t + 1];
        dk[64 + 2 * t]     = x0 * cs - x1 * sn;
        dk[64 + 2 * t + 1] = x1 * cs + x0 * sn;
    }
}

// ---------------------------------------------------------------------------
// Fused flash attention, fp32, non-causal, scale = 1.0.
// Q/K/V: [B*H][S][128].  O: [bs][h*128 + d] (row bs = b*2048+s).
// Block: 256 threads handles one (b,h) x 64 query rows.
// Key loop in tiles of 64. Online softmax.
// ---------------------------------------------------------------------------
#define QS_LD 132
#define FLASH_SMEM_BYTES ((3 * 64 * QS_LD + 64 * 64) * 4)

__global__ __launch_bounds__(256, 1)
void flash_attn(const float* __restrict__ Qg, const float* __restrict__ Kg,
                const float* __restrict__ Vg, float* __restrict__ Og)
{
    extern __shared__ float sm[];
    float* Qs = sm;                     // [64][132]
    float* Ks = sm + 64 * QS_LD;        // [64][132]
    float* Vs = sm + 2 * 64 * QS_LD;    // [64][132]
    float* Ps = sm + 3 * 64 * QS_LD;    // [64][64]

    const int tid = threadIdx.x;
    const int tx  = tid & 15;
    const int ty  = tid >> 4;
    const int bh  = blockIdx.y;         // b*16 + h
    const int b   = bh >> 4;
    const int h   = bh & 15;
    const int q0  = blockIdx.x * 64;

    // load Q tile
    {
        const int r = tid >> 2;
        const int c = (tid & 3) * 32;
        const float* src = Qg + ((size_t)bh * SLEN + q0 + r) * 128 + c;
        float* dst = Qs + r * QS_LD + c;
        #pragma unroll
        for (int q = 0; q < 8; ++q)
            *(float4*)(dst + q * 4) = *(const float4*)(src + q * 4);
    }

    float m_i[4], l_i[4];
    float o[4][8];
    #pragma unroll
    for (int i = 0; i < 4; ++i) {
        m_i[i] = -INFINITY;
        l_i[i] = 0.f;
        #pragma unroll
        for (int j = 0; j < 8; ++j) o[i][j] = 0.f;
    }
    __syncthreads();

    for (int kt = 0; kt < SLEN; kt += 64) {
        // load K, V tiles
        {
            const int r = tid >> 2;
            const int c = (tid & 3) * 32;
            const float* ksrc = Kg + ((size_t)bh * SLEN + kt + r) * 128 + c;
            const float* vsrc = Vg + ((size_t)bh * SLEN + kt + r) * 128 + c;
            float* kd = Ks + r * QS_LD + c;
            float* vd = Vs + r * QS_LD + c;
            #pragma unroll
            for (int q = 0; q < 8; ++q)
                *(float4*)(kd + q * 4) = *(const float4*)(ksrc + q * 4);
            #pragma unroll
            for (int q = 0; q < 8; ++q)
                *(float4*)(vd + q * 4) = *(const float4*)(vsrc + q * 4);
        }
        __syncthreads();

        // S = Q K^T, 4x4 microtile per thread
        float acc[4][4];
        #pragma unroll
        for (int i = 0; i < 4; ++i)
            #pragma unroll
            for (int j = 0; j < 4; ++j) acc[i][j] = 0.f;

        for (int d0 = 0; d0 < 128; d0 += 4) {
            float4 qv[4], kv[4];
            #pragma unroll
            for (int i = 0; i < 4; ++i)
                qv[i] = *(const float4*)(Qs + (ty * 4 + i) * QS_LD + d0);
            #pragma unroll
            for (int j = 0; j < 4; ++j)
                kv[j] = *(const float4*)(Ks + (tx * 4 + j) * QS_LD + d0);
            #pragma unroll
            for (int i = 0; i < 4; ++i)
                #pragma unroll
                for (int j = 0; j < 4; ++j) {
                    acc[i][j] = fmaf(qv[i].x, kv[j].x, acc[i][j]);
                    acc[i][j] = fmaf(qv[i].y, kv[j].y, acc[i][j]);
                    acc[i][j] = fmaf(qv[i].z, kv[j].z, acc[i][j]);
                    acc[i][j] = fmaf(qv[i].w, kv[j].w, acc[i][j]);
                }
        }

        // online softmax update (rows ty*4+i, reduce over 16 tx lanes)
        #pragma unroll
        for (int i = 0; i < 4; ++i) {
            float mx = fmaxf(fmaxf(acc[i][0], acc[i][1]), fmaxf(acc[i][2], acc[i][3]));
            #pragma unroll
            for (int off = 8; off > 0; off >>= 1)
                mx = fmaxf(mx, __shfl_xor_sync(0xffffffffu, mx, off));
            const float mnew = fmaxf(m_i[i], mx);
            float rs = 0.f;
            #pragma unroll
            for (int j = 0; j < 4; ++j) {
                acc[i][j] = __expf(acc[i][j] - mnew);
                rs += acc[i][j];
            }
            #pragma unroll
            for (int off = 8; off > 0; off >>= 1)
                rs += __shfl_xor_sync(0xffffffffu, rs, off);
            const float f = __expf(m_i[i] - mnew);
            l_i[i] = l_i[i] * f + rs;
            m_i[i] = mnew;
            #pragma unroll
            for (int j = 0; j < 8; ++j) o[i][j] *= f;
        }

        // write P
        #pragma unroll
        for (int i = 0; i < 4; ++i) {
            float4 pv = make_float4(acc[i][0], acc[i][1], acc[i][2], acc[i][3]);
            *(float4*)(Ps + (ty * 4 + i) * 64 + tx * 4) = pv;
        }
        __syncthreads();

        // O += P V
        #pragma unroll 2
        for (int c = 0; c < 64; ++c) {
            const float4 v0 = *(const float4*)(Vs + c * QS_LD + tx * 8);
            const float4 v1 = *(const float4*)(Vs + c * QS_LD + tx * 8 + 4);
            #pragma unroll
            for (int i = 0; i < 4; ++i) {
                const float p = Ps[(ty * 4 + i) * 64 + c];
                o[i][0] = fmaf(p, v0.x, o[i][0]);
                o[i][1] = fmaf(p, v0.y, o[i][1]);
                o[i][2] = fmaf(p, v0.z, o[i][2]);
                o[i][3] = fmaf(p, v0.w, o[i][3]);
                o[i][4] = fmaf(p, v1.x, o[i][4]);
                o[i][5] = fmaf(p, v1.y, o[i][5]);
                o[i][6] = fmaf(p, v1.z, o[i][6]);
                o[i][7] = fmaf(p, v1.w, o[i][7]);
            }
        }
        __syncthreads();
    }

    // epilogue: O row (b*2048 + q0 + r), col h*128 + tx*8 + j
    #pragma unroll
    for (int i = 0; i < 4; ++i) {
        const float inv = 1.f / l_i[i];
        float* dst = Og + ((size_t)b * SLEN + q0 + ty * 4 + i) * (NHEAD * V_D)
                        + h * V_D + tx * 8;
        float4 w0 = make_float4(o[i][0] * inv, o[i][1] * inv, o[i][2] * inv, o[i][3] * inv);
        float4 w1 = make_float4(o[i][4] * inv, o[i][5] * inv, o[i][6] * inv, o[i][7] * inv);
        *(float4*)dst       = w0;
        *(float4*)(dst + 4) = w1;
    }
}

// ---------------------------------------------------------------------------
extern "C" void kernel_launch(void* const* d_in, const int* in_sizes, int n_in,
                              void* d_out, int out_size)
{
    const float* x    = (const float*)d_in[0];
    const float* q_a  = (const float*)d_in[1];
    const float* q_b  = (const float*)d_in[2];
    const float* kv_a = (const float*)d_in[3];
    const float* kv_b = (const float*)d_in[4];
    const float* o_w  = (const float*)d_in[5];
    float* out = (float*)d_out;

    float *Xq, *Q, *CKV, *KVB, *Qb, *Kb, *Vb, *O;
    cudaGetSymbolAddress((void**)&Xq,  g_Xq);
    cudaGetSymbolAddress((void**)&Q,   g_Q);
    cudaGetSymbolAddress((void**)&CKV, g_CKV);
    cudaGetSymbolAddress((void**)&KVB, g_KVB);
    cudaGetSymbolAddress((void**)&Qb,  g_Qb);
    cudaGetSymbolAddress((void**)&Kb,  g_Kb);
    cudaGetSymbolAddress((void**)&Vb,  g_Vb);
    cudaGetSymbolAddress((void**)&O,   g_O);

    cudaFuncSetAttribute(flash_attn, cudaFuncAttributeMaxDynamicSharedMemorySize,
                         FLASH_SMEM_BYTES);

    const dim3 tpb(256);
    // 1) Xq = x @ q_a_w^T         (4096 x 1536, K=2048)
    sgemm_nt<<<dim3(QRANK / 128, MROWS / 128), tpb>>>(x, q_a, Xq,
        MROWS, QRANK, EMB, EMB, EMB, QRANK);
    // 2) Q = Xq @ q_b_w^T         (4096 x 2048, K=1536)
    sgemm_nt<<<dim3((NHEAD * QK_D) / 128, MROWS / 128), tpb>>>(Xq, q_b, Q,
        MROWS, NHEAD * QK_D, QRANK, QRANK, QRANK, NHEAD * QK_D);
    // 3) CKV = x @ kv_a_w^T       (4096 x 576, K=2048)
    sgemm_nt<<<dim3((576 + 127) / 128, MROWS / 128), tpb>>>(x, kv_a, CKV,
        MROWS, 576, EMB, EMB, EMB, 576);
    // 4) KVB = CKV[:, :512] @ kv_b_w^T  (4096 x 3072, K=512)
    sgemm_nt<<<dim3(3072 / 128, MROWS / 128), tpb>>>(CKV, kv_b, KVB,
        MROWS, 3072, KVRANK, 576, KVRANK, 3072);
    // 5) repack + rope
    build_q<<<MROWS, dim3(64, NHEAD)>>>(Q, Qb);
    build_kv<<<MROWS, dim3(64, NHEAD)>>>(KVB, CKV, Kb, Vb);
    // 6) attention
    flash_attn<<<dim3(SLEN / 64, BATCH * NHEAD), tpb, FLASH_SMEM_BYTES>>>(Qb, Kb, Vb, O);
    // 7) out = O @ o_w^T          (4096 x 2048, K=2048)
    sgemm_nt<<<dim3(EMB / 128, MROWS / 128), tpb>>>(O, o_w, out,
        MROWS, EMB, NHEAD * V_D, NHEAD * V_D, NHEAD * V_D, EMB);
}

// round 3
// speedup vs baseline: 1.2962x; 1.2962x over previous
#include <cuda_runtime.h>
#include <cuda_bf16.h>
#include <math.h>
#include <stdint.h>

// ---------------------------------------------------------------------------
// Problem constants
// ---------------------------------------------------------------------------
#define BATCH   2
#define SLEN    2048
#define EMB     2048
#define NHEAD   16
#define QRANK   1536
#define KVRANK  512
#define QK_D    128
#define V_D     128
#define MROWS   (BATCH * SLEN)        // 4096

// ------------------------- fp32 scratch -----------------------------------
__device__ float g_Xq [(size_t)MROWS * QRANK];
__device__ float g_Q  [(size_t)MROWS * (NHEAD * QK_D)];
__device__ float g_CKV[(size_t)MROWS * 576];
__device__ float g_KVB[(size_t)MROWS * 3072];
__device__ float g_Qb [(size_t)BATCH * NHEAD * SLEN * QK_D];
__device__ float g_Kb [(size_t)BATCH * NHEAD * SLEN * QK_D];
__device__ float g_Vb [(size_t)BATCH * NHEAD * SLEN * V_D];
__device__ float g_O  [(size_t)MROWS * (NHEAD * V_D)];

// ------------------------- bf16 hi/lo split buffers -----------------------
__device__ __nv_bfloat16 g_x_hi  [(size_t)MROWS * EMB];
__device__ __nv_bfloat16 g_x_lo  [(size_t)MROWS * EMB];
__device__ __nv_bfloat16 g_qa_hi [(size_t)QRANK * EMB];
__device__ __nv_bfloat16 g_qa_lo [(size_t)QRANK * EMB];
__device__ __nv_bfloat16 g_qb_hi [(size_t)(NHEAD * QK_D) * QRANK];
__device__ __nv_bfloat16 g_qb_lo [(size_t)(NHEAD * QK_D) * QRANK];
__device__ __nv_bfloat16 g_kva_hi[(size_t)576 * EMB];
__device__ __nv_bfloat16 g_kva_lo[(size_t)576 * EMB];
__device__ __nv_bfloat16 g_kvb_hi[(size_t)3072 * KVRANK];
__device__ __nv_bfloat16 g_kvb_lo[(size_t)3072 * KVRANK];
__device__ __nv_bfloat16 g_ow_hi [(size_t)EMB * (NHEAD * V_D)];
__device__ __nv_bfloat16 g_ow_lo [(size_t)EMB * (NHEAD * V_D)];
__device__ __nv_bfloat16 g_Xq_hi [(size_t)MROWS * QRANK];
__device__ __nv_bfloat16 g_Xq_lo [(size_t)MROWS * QRANK];
__device__ __nv_bfloat16 g_ckv_hi[(size_t)MROWS * KVRANK];
__device__ __nv_bfloat16 g_ckv_lo[(size_t)MROWS * KVRANK];
__device__ __nv_bfloat16 g_O_hi  [(size_t)MROWS * (NHEAD * V_D)];
__device__ __nv_bfloat16 g_O_lo  [(size_t)MROWS * (NHEAD * V_D)];

// ---------------------------------------------------------------------------
// PTX helpers (all arch-agnostic: sm_80-era features, legal at compute_103)
// ---------------------------------------------------------------------------
__device__ __forceinline__ uint32_t cvta_s(const void* p) {
    return (uint32_t)__cvta_generic_to_shared(p);
}
__device__ __forceinline__ void cp16(uint32_t dst, const void* src) {
    asm volatile("cp.async.cg.shared.global [%0], [%1], 16;"
                 :: "r"(dst), "l"(src) : "memory");
}
__device__ __forceinline__ void cp16_pred(uint32_t dst, const void* src, bool valid) {
    const int sz = valid ? 16 : 0;   // zero-fill when invalid
    asm volatile("cp.async.cg.shared.global [%0], [%1], 16, %2;"
                 :: "r"(dst), "l"(src), "r"(sz) : "memory");
}
__device__ __forceinline__ void cp_commit() {
    asm volatile("cp.async.commit_group;" ::: "memory");
}

__device__ __forceinline__ void ldm_x4(uint32_t& r0, uint32_t& r1, uint32_t& r2,
                                       uint32_t& r3, uint32_t addr) {
    asm volatile("ldmatrix.sync.aligned.m8n8.x4.shared.b16 {%0,%1,%2,%3}, [%4];"
                 : "=r"(r0), "=r"(r1), "=r"(r2), "=r"(r3) : "r"(addr));
}
__device__ __forceinline__ void ldm_x2(uint32_t& r0, uint32_t& r1, uint32_t addr) {
    asm volatile("ldmatrix.sync.aligned.m8n8.x2.shared.b16 {%0,%1}, [%2];"
                 : "=r"(r0), "=r"(r1) : "r"(addr));
}
__device__ __forceinline__ void mma_bf16(float* c, const uint32_t* a,
                                         const uint32_t* b) {
    asm volatile(
        "mma.sync.aligned.m16n8k16.row.col.f32.bf16.bf16.f32 "
        "{%0,%1,%2,%3}, {%4,%5,%6,%7}, {%8,%9}, {%0,%1,%2,%3};"
        : "+f"(c[0]), "+f"(c[1]), "+f"(c[2]), "+f"(c[3])
        : "r"(a[0]), "r"(a[1]), "r"(a[2]), "r"(a[3]), "r"(b[0]), "r"(b[1]));
}

// ---------------------------------------------------------------------------
// HMMA split-bf16 GEMM (NT): C[M,N] = A[M,K] @ B[N,K]^T
//   CTA tile 128x128, BK=32, 8 warps (2x4), warp tile 64x32.
//   Per 16-k chunk per warp: 48 mma (Ahi*Bhi + Ahi*Blo + Alo*Bhi).
// smem per stage: 4 tiles of [128][40] bf16 (padded rows, conflict-free).
// ---------------------------------------------------------------------------
#define LDP 40                            // padded row length (elements)
#define TILE_B (128 * LDP * 2)            // 10240 bytes per tile
#define STAGE_B (4 * TILE_B)              // 40960 bytes per stage
#define GEMM_SMEM (2 * STAGE_B)           // 81920

__device__ __forceinline__ void gload_stage(
    uint32_t sb, const __nv_bfloat16* Ahi, const __nv_bfloat16* Alo,
    const __nv_bfloat16* Bhi, const __nv_bfloat16* Blo,
    int bm, int bn, int k0, int K, int N, int tid)
{
    // each matrix: 128 rows x 4 chunks of 16B
    #pragma unroll
    for (int idx = tid; idx < 512; idx += 256) {
        const int r = idx >> 2, c = idx & 3;
        const uint32_t so = (uint32_t)(r * LDP * 2 + c * 16);
        const size_t ga = (size_t)(bm + r) * K + k0 + c * 8;
        cp16(sb + 0 * TILE_B + so, Ahi + ga);
        cp16(sb + 1 * TILE_B + so, Alo + ga);
        const bool v = (bn + r) < N;
        const size_t gb = v ? ((size_t)(bn + r) * K + k0 + c * 8) : 0;
        cp16_pred(sb + 2 * TILE_B + so, Bhi + gb, v);
        cp16_pred(sb + 3 * TILE_B + so, Blo + gb, v);
    }
}

__global__ __launch_bounds__(256, 2)
void gemm_mma(const __nv_bfloat16* __restrict__ Ahi, const __nv_bfloat16* __restrict__ Alo,
              const __nv_bfloat16* __restrict__ Bhi, const __nv_bfloat16* __restrict__ Blo,
              float* __restrict__ C, int N, int K, int ldc)
{
    extern __shared__ char smraw[];
    const uint32_t sbase = cvta_s(smraw);

    const int tid  = threadIdx.x;
    const int wid  = tid >> 5;
    const int lane = tid & 31;
    const int warp_m = (wid >> 2) * 64;     // 0 or 64
    const int warp_n = (wid & 3) * 32;      // 0,32,64,96
    const int bm = blockIdx.y * 128;
    const int bn = blockIdx.x * 128;
    const int nk = K / 32;

    float acc[4][4][4];
    #pragma unroll
    for (int i = 0; i < 4; ++i)
        #pragma unroll
        for (int j = 0; j < 4; ++j)
            #pragma unroll
            for (int q = 0; q < 4; ++q) acc[i][j][q] = 0.f;

    gload_stage(sbase, Ahi, Alo, Bhi, Blo, bm, bn, 0, K, N, tid);
    cp_commit();

    // precomputed ldmatrix lane offsets (element units)
    const int a_row = lane & 15;            // row within 16
    const int a_coff = (lane >> 4) << 3;    // 0 or 8
    const int b_row = lane & 7;
    const int b_coff = ((lane >> 3) & 1) << 3;

    for (int i = 0; i < nk; ++i) {
        if (i + 1 < nk) {
            gload_stage(sbase + ((i + 1) & 1) * STAGE_B, Ahi, Alo, Bhi, Blo,
                        bm, bn, (i + 1) * 32, K, N, tid);
            cp_commit();
            asm volatile("cp.async.wait_group 1;" ::: "memory");
        } else {
            asm volatile("cp.async.wait_group 0;" ::: "memory");
        }
        __syncthreads();

        const uint32_t sb = sbase + (i & 1) * STAGE_B;
        #pragma unroll
        for (int kc = 0; kc < 2; ++kc) {
            const int kel = kc * 16;
            uint32_t ah[4][4], al[4][4];
            #pragma unroll
            for (int mi = 0; mi < 4; ++mi) {
                const uint32_t ao = (uint32_t)((warp_m + mi * 16 + a_row) * LDP
                                               + kel + a_coff) * 2;
                ldm_x4(ah[mi][0], ah[mi][1], ah[mi][2], ah[mi][3], sb + ao);
                ldm_x4(al[mi][0], al[mi][1], al[mi][2], al[mi][3],
                       sb + TILE_B + ao);
            }
            #pragma unroll
            for (int ni = 0; ni < 4; ++ni) {
                const uint32_t bo = (uint32_t)((warp_n + ni * 8 + b_row) * LDP
                                               + kel + b_coff) * 2;
                uint32_t bh[2], bl[2];
                ldm_x2(bh[0], bh[1], sb + 2 * TILE_B + bo);
                ldm_x2(bl[0], bl[1], sb + 3 * TILE_B + bo);
                #pragma unroll
                for (int mi = 0; mi < 4; ++mi) {
                    mma_bf16(acc[mi][ni], ah[mi], bh);
                    mma_bf16(acc[mi][ni], ah[mi], bl);
                    mma_bf16(acc[mi][ni], al[mi], bh);
                }
            }
        }
        __syncthreads();
    }

    // epilogue
    const int er = lane >> 2;
    const int ec = (lane & 3) * 2;
    #pragma unroll
    for (int mi = 0; mi < 4; ++mi) {
        #pragma unroll
        for (int ni = 0; ni < 4; ++ni) {
            const int col = bn + warp_n + ni * 8 + ec;
            if (col < N) {
                const int r0 = bm + warp_m + mi * 16 + er;
                *(float2*)(C + (size_t)r0 * ldc + col) =
                    make_float2(acc[mi][ni][0], acc[mi][ni][1]);
                *(float2*)(C + (size_t)(r0 + 8) * ldc + col) =
                    make_float2(acc[mi][ni][2], acc[mi][ni][3]);
            }
        }
    }
}

// ---------------------------------------------------------------------------
// fp32 -> (bf16 hi, bf16 lo) split kernels
// ---------------------------------------------------------------------------
union BV4 { __nv_bfloat16 b[4]; ushort4 u; };

__global__ void split_f32(const float* __restrict__ s, __nv_bfloat16* __restrict__ hi,
                          __nv_bfloat16* __restrict__ lo, int n4)
{
    const int i = blockIdx.x * blockDim.x + threadIdx.x;
    if (i >= n4) return;
    const float4 v = ((const float4*)s)[i];
    const float vv[4] = { v.x, v.y, v.z, v.w };
    BV4 H, L;
    #pragma unroll
    for (int j = 0; j < 4; ++j) {
        H.b[j] = __float2bfloat16(vv[j]);
        L.b[j] = __float2bfloat16(vv[j] - __bfloat162float(H.b[j]));
    }
    ((ushort4*)hi)[i] = H.u;
    ((ushort4*)lo)[i] = L.u;
}

__global__ void split_ckv(const float* __restrict__ s, __nv_bfloat16* __restrict__ hi,
                          __nv_bfloat16* __restrict__ lo)
{
    const int i = blockIdx.x * blockDim.x + threadIdx.x;
    const int r  = i >> 7;
    const int c4 = (i & 127) * 4;
    const float4 v = *(const float4*)(s + (size_t)r * 576 + c4);
    const float vv[4] = { v.x, v.y, v.z, v.w };
    BV4 H, L;
    #pragma unroll
    for (int j = 0; j < 4; ++j) {
        H.b[j] = __float2bfloat16(vv[j]);
        L.b[j] = __float2bfloat16(vv[j] - __bfloat162float(H.b[j]));
    }
    const size_t o = ((size_t)r * 512 + c4) / 4;
    ((ushort4*)hi)[o] = H.u;
    ((ushort4*)lo)[o] = L.u;
}

// ---------------------------------------------------------------------------
// Repack + RoPE
// ---------------------------------------------------------------------------
__global__ void build_q(const float* __restrict__ Q, float* __restrict__ Qb)
{
    const int bs = blockIdx.x;
    const int b  = bs >> 11;
    const int s  = bs & 2047;
    const int h  = threadIdx.y;
    const int t  = threadIdx.x;

    const float* src = Q + (size_t)bs * (NHEAD * QK_D) + h * QK_D;
    float* dst = Qb + ((size_t)(b * NHEAD + h) * SLEN + s) * QK_D;

    dst[t] = src[t];

    if (t < 32) {
        const float theta = powf(10000.f, -((float)(2 * t)) / 64.f);
        float sn, cs;
        sincosf((float)s * theta, &sn, &cs);
        const float x0 = src[64 + 2 * t];
        const float x1 = src[64 + 2 * t + 1];
        dst[64 + 2 * t]     = x0 * cs - x1 * sn;
        dst[64 + 2 * t + 1] = x1 * cs + x0 * sn;
    }
}

__global__ void build_kv(const float* __restrict__ KVB, const float* __restrict__ CKV,
                         float* __restrict__ Kb, float* __restrict__ Vb)
{
    const int bs = blockIdx.x;
    const int b  = bs >> 11;
    const int s  = bs & 2047;
    const int h  = threadIdx.y;
    const int t  = threadIdx.x;

    const float* kv = KVB + (size_t)bs * 3072 + h * 192;
    float* dk = Kb + ((size_t)(b * NHEAD + h) * SLEN + s) * QK_D;
    float* dv = Vb + ((size_t)(b * NHEAD + h) * SLEN + s) * V_D;

    dk[t]      = kv[t];
    dv[t]      = kv[64 + t];
    dv[64 + t] = kv[128 + t];

    if (t < 32) {
        const float theta = powf(10000.f, -((float)(2 * t)) / 64.f);
        float sn, cs;
        sincosf((float)s * theta, &sn, &cs);
        const float* kr = CKV + (size_t)bs * 576 + 512;
        const float x0 = kr[2 * t];
        const float x1 = kr[2 * t + 1];
        dk[64 + 2 * t]     = x0 * cs - x1 * sn;
        dk[64 + 2 * t + 1] = x1 * cs + x0 * sn;
    }
}

// ---------------------------------------------------------------------------
// Fused flash attention (fp32) — unchanged
// ---------------------------------------------------------------------------
#define QS_LD 132
#define FLASH_SMEM_BYTES ((3 * 64 * QS_LD + 64 * 64) * 4)

__global__ __launch_bounds__(256, 1)
void flash_attn(const float* __restrict__ Qg, const float* __restrict__ Kg,
                const float* __restrict__ Vg, float* __restrict__ Og)
{
    extern __shared__ float sm[];
    float* Qs = sm;
    float* Ks = sm + 64 * QS_LD;
    float* Vs = sm + 2 * 64 * QS_LD;
    float* Ps = sm + 3 * 64 * QS_LD;

    const int tid = threadIdx.x;
    const int tx  = tid & 15;
    const int ty  = tid >> 4;
    const int bh  = blockIdx.y;
    const int b   = bh >> 4;
    const int h   = bh & 15;
    const int q0  = blockIdx.x * 64;

    {
        const int r = tid >> 2;
        const int c = (tid & 3) * 32;
        const float* src = Qg + ((size_t)bh * SLEN + q0 + r) * 128 + c;
        float* dst = Qs + r * QS_LD + c;
        #pragma unroll
        for (int q = 0; q < 8; ++q)
            *(float4*)(dst + q * 4) = *(const float4*)(src + q * 4);
    }

    float m_i[4], l_i[4];
    float o[4][8];
    #pragma unroll
    for (int i = 0; i < 4; ++i) {
        m_i[i] = -INFINITY;
        l_i[i] = 0.f;
        #pragma unroll
        for (int j = 0; j < 8; ++j) o[i][j] = 0.f;
    }
    __syncthreads();

    for (int kt = 0; kt < SLEN; kt += 64) {
        {
            const int r = tid >> 2;
            const int c = (tid & 3) * 32;
            const float* ksrc = Kg + ((size_t)bh * SLEN + kt + r) * 128 + c;
            const float* vsrc = Vg + ((size_t)bh * SLEN + kt + r) * 128 + c;
            float* kd = Ks + r * QS_LD + c;
            float* vd = Vs + r * QS_LD + c;
            #pragma unroll
            for (int q = 0; q < 8; ++q)
                *(float4*)(kd + q * 4) = *(const float4*)(ksrc + q * 4);
            #pragma unroll
            for (int q = 0; q < 8; ++q)
                *(float4*)(vd + q * 4) = *(const float4*)(vsrc + q * 4);
        }
        __syncthreads();

        float acc[4][4];
        #pragma unroll
        for (int i = 0; i < 4; ++i)
            #pragma unroll
            for (int j = 0; j < 4; ++j) acc[i][j] = 0.f;

        for (int d0 = 0; d0 < 128; d0 += 4) {
            float4 qv[4], kv[4];
            #pragma unroll
            for (int i = 0; i < 4; ++i)
                qv[i] = *(const float4*)(Qs + (ty * 4 + i) * QS_LD + d0);
            #pragma unroll
            for (int j = 0; j < 4; ++j)
                kv[j] = *(const float4*)(Ks + (tx * 4 + j) * QS_LD + d0);
            #pragma unroll
            for (int i = 0; i < 4; ++i)
                #pragma unroll
                for (int j = 0; j < 4; ++j) {
                    acc[i][j] = fmaf(qv[i].x, kv[j].x, acc[i][j]);
                    acc[i][j] = fmaf(qv[i].y, kv[j].y, acc[i][j]);
                    acc[i][j] = fmaf(qv[i].z, kv[j].z, acc[i][j]);
                    acc[i][j] = fmaf(qv[i].w, kv[j].w, acc[i][j]);
                }
        }

        #pragma unroll
        for (int i = 0; i < 4; ++i) {
            float mx = fmaxf(fmaxf(acc[i][0], acc[i][1]), fmaxf(acc[i][2], acc[i][3]));
            #pragma unroll
            for (int off = 8; off > 0; off >>= 1)
                mx = fmaxf(mx, __shfl_xor_sync(0xffffffffu, mx, off));
            const float mnew = fmaxf(m_i[i], mx);
            float rs = 0.f;
            #pragma unroll
            for (int j = 0; j < 4; ++j) {
                acc[i][j] = __expf(acc[i][j] - mnew);
                rs += acc[i][j];
            }
            #pragma unroll
            for (int off = 8; off > 0; off >>= 1)
                rs += __shfl_xor_sync(0xffffffffu, rs, off);
            const float f = __expf(m_i[i] - mnew);
            l_i[i] = l_i[i] * f + rs;
            m_i[i] = mnew;
            #pragma unroll
            for (int j = 0; j < 8; ++j) o[i][j] *= f;
        }

        #pragma unroll
        for (int i = 0; i < 4; ++i) {
            float4 pv = make_float4(acc[i][0], acc[i][1], acc[i][2], acc[i][3]);
            *(float4*)(Ps + (ty * 4 + i) * 64 + tx * 4) = pv;
        }
        __syncthreads();

        #pragma unroll 2
        for (int c = 0; c < 64; ++c) {
            const float4 v0 = *(const float4*)(Vs + c * QS_LD + tx * 8);
            const float4 v1 = *(const float4*)(Vs + c * QS_LD + tx * 8 + 4);
            #pragma unroll
            for (int i = 0; i < 4; ++i) {
                const float p = Ps[(ty * 4 + i) * 64 + c];
                o[i][0] = fmaf(p, v0.x, o[i][0]);
                o[i][1] = fmaf(p, v0.y, o[i][1]);
                o[i][2] = fmaf(p, v0.z, o[i][2]);
                o[i][3] = fmaf(p, v0.w, o[i][3]);
                o[i][4] = fmaf(p, v1.x, o[i][4]);
                o[i][5] = fmaf(p, v1.y, o[i][5]);
                o[i][6] = fmaf(p, v1.z, o[i][6]);
                o[i][7] = fmaf(p, v1.w, o[i][7]);
            }
        }
        __syncthreads();
    }

    #pragma unroll
    for (int i = 0; i < 4; ++i) {
        const float inv = 1.f / l_i[i];
        float* dst = Og + ((size_t)b * SLEN + q0 + ty * 4 + i) * (NHEAD * V_D)
                        + h * V_D + tx * 8;
        float4 w0 = make_float4(o[i][0] * inv, o[i][1] * inv, o[i][2] * inv, o[i][3] * inv);
        float4 w1 = make_float4(o[i][4] * inv, o[i][5] * inv, o[i][6] * inv, o[i][7] * inv);
        *(float4*)dst       = w0;
        *(float4*)(dst + 4) = w1;
    }
}

// ---------------------------------------------------------------------------
extern "C" void kernel_launch(void* const* d_in, const int* in_sizes, int n_in,
                              void* d_out, int out_size)
{
    const float* x    = (const float*)d_in[0];
    const float* q_a  = (const float*)d_in[1];
    const float* q_b  = (const float*)d_in[2];
    const float* kv_a = (const float*)d_in[3];
    const float* kv_b = (const float*)d_in[4];
    const float* o_w  = (const float*)d_in[5];
    float* out = (float*)d_out;

    float *Xq, *Q, *CKV, *KVB, *Qb, *Kb, *Vb, *O;
    cudaGetSymbolAddress((void**)&Xq,  g_Xq);
    cudaGetSymbolAddress((void**)&Q,   g_Q);
    cudaGetSymbolAddress((void**)&CKV, g_CKV);
    cudaGetSymbolAddress((void**)&KVB, g_KVB);
    cudaGetSymbolAddress((void**)&Qb,  g_Qb);
    cudaGetSymbolAddress((void**)&Kb,  g_Kb);
    cudaGetSymbolAddress((void**)&Vb,  g_Vb);
    cudaGetSymbolAddress((void**)&O,   g_O);

    __nv_bfloat16 *x_hi, *x_lo, *qa_hi, *qa_lo, *qb_hi, *qb_lo, *kva_hi, *kva_lo;
    __nv_bfloat16 *kvb_hi, *kvb_lo, *ow_hi, *ow_lo, *Xq_hi, *Xq_lo, *ckv_hi, *ckv_lo;
    __nv_bfloat16 *O_hi, *O_lo;
    cudaGetSymbolAddress((void**)&x_hi,   g_x_hi);
    cudaGetSymbolAddress((void**)&x_lo,   g_x_lo);
    cudaGetSymbolAddress((void**)&qa_hi,  g_qa_hi);
    cudaGetSymbolAddress((void**)&qa_lo,  g_qa_lo);
    cudaGetSymbolAddress((void**)&qb_hi,  g_qb_hi);
    cudaGetSymbolAddress((void**)&qb_lo,  g_qb_lo);
    cudaGetSymbolAddress((void**)&kva_hi, g_kva_hi);
    cudaGetSymbolAddress((void**)&kva_lo, g_kva_lo);
    cudaGetSymbolAddress((void**)&kvb_hi, g_kvb_hi);
    cudaGetSymbolAddress((void**)&kvb_lo, g_kvb_lo);
    cudaGetSymbolAddress((void**)&ow_hi,  g_ow_hi);
    cudaGetSymbolAddress((void**)&ow_lo,  g_ow_lo);
    cudaGetSymbolAddress((void**)&Xq_hi,  g_Xq_hi);
    cudaGetSymbolAddress((void**)&Xq_lo,  g_Xq_lo);
    cudaGetSymbolAddress((void**)&ckv_hi, g_ckv_hi);
    cudaGetSymbolAddress((void**)&ckv_lo, g_ckv_lo);
    cudaGetSymbolAddress((void**)&O_hi,   g_O_hi);
    cudaGetSymbolAddress((void**)&O_lo,   g_O_lo);

    cudaFuncSetAttribute(flash_attn, cudaFuncAttributeMaxDynamicSharedMemorySize,
                         FLASH_SMEM_BYTES);
    cudaFuncSetAttribute(gemm_mma, cudaFuncAttributeMaxDynamicSharedMemorySize,
                         GEMM_SMEM);

    const int TPB = 256;
    #define SPLIT(src, hi, lo, n) \
        split_f32<<<((n) / 4 + TPB - 1) / TPB, TPB>>>(src, hi, lo, (n) / 4)

    SPLIT(x,    x_hi,   x_lo,   MROWS * EMB);
    SPLIT(q_a,  qa_hi,  qa_lo,  QRANK * EMB);
    SPLIT(q_b,  qb_hi,  qb_lo,  (NHEAD * QK_D) * QRANK);
    SPLIT(kv_a, kva_hi, kva_lo, 576 * EMB);
    SPLIT(kv_b, kvb_hi, kvb_lo, 3072 * KVRANK);
    SPLIT(o_w,  ow_hi,  ow_lo,  EMB * (NHEAD * V_D));

    // 1) Xq = x @ q_a^T   (4096 x 1536, K=2048)
    gemm_mma<<<dim3(12, 32), 256, GEMM_SMEM>>>(x_hi, x_lo, qa_hi, qa_lo,
                                               Xq, QRANK, EMB, QRANK);
    SPLIT(Xq, Xq_hi, Xq_lo, MROWS * QRANK);
    // 2) Q = Xq @ q_b^T   (4096 x 2048, K=1536)
    gemm_mma<<<dim3(16, 32), 256, GEMM_SMEM>>>(Xq_hi, Xq_lo, qb_hi, qb_lo,
                                               Q, NHEAD * QK_D, QRANK, NHEAD * QK_D);
    // 3) CKV = x @ kv_a^T (4096 x 576, K=2048)
    gemm_mma<<<dim3(5, 32), 256, GEMM_SMEM>>>(x_hi, x_lo, kva_hi, kva_lo,
                                              CKV, 576, EMB, 576);
    split_ckv<<<(MROWS * 128) / TPB, TPB>>>(CKV, ckv_hi, ckv_lo);
    // 4) KVB = CKV512 @ kv_b^T (4096 x 3072, K=512)
    gemm_mma<<<dim3(24, 32), 256, GEMM_SMEM>>>(ckv_hi, ckv_lo, kvb_hi, kvb_lo,
                                               KVB, 3072, KVRANK, 3072);
    // 5) repack + rope
    build_q<<<MROWS, dim3(64, NHEAD)>>>(Q, Qb);
    build_kv<<<MROWS, dim3(64, NHEAD)>>>(KVB, CKV, Kb, Vb);
    // 6) attention
    flash_attn<<<dim3(SLEN / 64, BATCH * NHEAD), 256, FLASH_SMEM_BYTES>>>(Qb, Kb, Vb, O);
    // 7) out = O @ o_w^T  (4096 x 2048, K=2048)
    SPLIT(O, O_hi, O_lo, MROWS * (NHEAD * V_D));
    gemm_mma<<<dim3(16, 32), 256, GEMM_SMEM>>>(O_hi, O_lo, ow_hi, ow_lo,
                                               out, EMB, NHEAD * V_D, EMB);
    #undef SPLIT
}

// round 4
// speedup vs baseline: 3.7112x; 2.8631x over previous
#include <cuda_runtime.h>
#include <cuda_bf16.h>
#include <math.h>
#include <stdint.h>

// ---------------------------------------------------------------------------
// Problem constants
// ---------------------------------------------------------------------------
#define BATCH   2
#define SLEN    2048
#define EMB     2048
#define NHEAD   16
#define QRANK   1536
#define KVRANK  512
#define QK_D    128
#define V_D     128
#define MROWS   (BATCH * SLEN)        // 4096
#define BHN     (BATCH * NHEAD)       // 32

// ------------------------- fp32 scratch -----------------------------------
__device__ float g_Xq [(size_t)MROWS * QRANK];
__device__ float g_Q  [(size_t)MROWS * (NHEAD * QK_D)];
__device__ float g_CKV[(size_t)MROWS * 576];
__device__ float g_KVB[(size_t)MROWS * 3072];

// ------------------------- bf16 hi/lo split buffers -----------------------
__device__ __nv_bfloat16 g_x_hi  [(size_t)MROWS * EMB];
__device__ __nv_bfloat16 g_x_lo  [(size_t)MROWS * EMB];
__device__ __nv_bfloat16 g_qa_hi [(size_t)QRANK * EMB];
__device__ __nv_bfloat16 g_qa_lo [(size_t)QRANK * EMB];
__device__ __nv_bfloat16 g_qb_hi [(size_t)(NHEAD * QK_D) * QRANK];
__device__ __nv_bfloat16 g_qb_lo [(size_t)(NHEAD * QK_D) * QRANK];
__device__ __nv_bfloat16 g_kva_hi[(size_t)576 * EMB];
__device__ __nv_bfloat16 g_kva_lo[(size_t)576 * EMB];
__device__ __nv_bfloat16 g_kvb_hi[(size_t)3072 * KVRANK];
__device__ __nv_bfloat16 g_kvb_lo[(size_t)3072 * KVRANK];
__device__ __nv_bfloat16 g_ow_hi [(size_t)EMB * (NHEAD * V_D)];
__device__ __nv_bfloat16 g_ow_lo [(size_t)EMB * (NHEAD * V_D)];
__device__ __nv_bfloat16 g_Xq_hi [(size_t)MROWS * QRANK];
__device__ __nv_bfloat16 g_Xq_lo [(size_t)MROWS * QRANK];
__device__ __nv_bfloat16 g_ckv_hi[(size_t)MROWS * KVRANK];
__device__ __nv_bfloat16 g_ckv_lo[(size_t)MROWS * KVRANK];
// attention operands / results (bf16 hi/lo)
__device__ __nv_bfloat16 g_Qb_hi [(size_t)BHN * SLEN * QK_D];
__device__ __nv_bfloat16 g_Qb_lo [(size_t)BHN * SLEN * QK_D];
__device__ __nv_bfloat16 g_Kb_hi [(size_t)BHN * SLEN * QK_D];
__device__ __nv_bfloat16 g_Kb_lo [(size_t)BHN * SLEN * QK_D];
__device__ __nv_bfloat16 g_Vt_hi [(size_t)BHN * V_D * SLEN];
__device__ __nv_bfloat16 g_Vt_lo [(size_t)BHN * V_D * SLEN];
__device__ __nv_bfloat16 g_O_hi  [(size_t)MROWS * (NHEAD * V_D)];
__device__ __nv_bfloat16 g_O_lo  [(size_t)MROWS * (NHEAD * V_D)];

// ---------------------------------------------------------------------------
// PTX helpers (arch-agnostic, legal at compute_103)
// ---------------------------------------------------------------------------
__device__ __forceinline__ uint32_t cvta_s(const void* p) {
    return (uint32_t)__cvta_generic_to_shared(p);
}
__device__ __forceinline__ void cp16(uint32_t dst, const void* src) {
    asm volatile("cp.async.cg.shared.global [%0], [%1], 16;"
                 :: "r"(dst), "l"(src) : "memory");
}
__device__ __forceinline__ void cp16_pred(uint32_t dst, const void* src, bool valid) {
    const int sz = valid ? 16 : 0;
    asm volatile("cp.async.cg.shared.global [%0], [%1], 16, %2;"
                 :: "r"(dst), "l"(src), "r"(sz) : "memory");
}
__device__ __forceinline__ void cp_commit() {
    asm volatile("cp.async.commit_group;" ::: "memory");
}
__device__ __forceinline__ void ldm_x4(uint32_t* r, uint32_t addr) {
    asm volatile("ldmatrix.sync.aligned.m8n8.x4.shared.b16 {%0,%1,%2,%3}, [%4];"
                 : "=r"(r[0]), "=r"(r[1]), "=r"(r[2]), "=r"(r[3]) : "r"(addr));
}
__device__ __forceinline__ void ldm_x2(uint32_t& r0, uint32_t& r1, uint32_t addr) {
    asm volatile("ldmatrix.sync.aligned.m8n8.x2.shared.b16 {%0,%1}, [%2];"
                 : "=r"(r0), "=r"(r1) : "r"(addr));
}
__device__ __forceinline__ void mma_bf16(float* c, const uint32_t* a,
                                         const uint32_t* b) {
    asm volatile(
        "mma.sync.aligned.m16n8k16.row.col.f32.bf16.bf16.f32 "
        "{%0,%1,%2,%3}, {%4,%5,%6,%7}, {%8,%9}, {%0,%1,%2,%3};"
        : "+f"(c[0]), "+f"(c[1]), "+f"(c[2]), "+f"(c[3])
        : "r"(a[0]), "r"(a[1]), "r"(a[2]), "r"(a[3]), "r"(b[0]), "r"(b[1]));
}
__device__ __forceinline__ uint32_t pack_bf2(float lo, float hi) {
    uint32_t r;
    asm("cvt.rn.bf16x2.f32 %0, %1, %2;" : "=r"(r) : "f"(hi), "f"(lo));
    return r;
}
__device__ __forceinline__ float bf_res(float v) {
    return v - __bfloat162float(__float2bfloat16(v));
}

// ---------------------------------------------------------------------------
// HMMA split-bf16 GEMM (NT): C[M,N] = A[M,K] @ B[N,K]^T   (unchanged R3)
// ---------------------------------------------------------------------------
#define LDP 40
#define TILE_B (128 * LDP * 2)
#define STAGE_B (4 * TILE_B)
#define GEMM_SMEM (2 * STAGE_B)

__device__ __forceinline__ void gload_stage(
    uint32_t sb, const __nv_bfloat16* Ahi, const __nv_bfloat16* Alo,
    const __nv_bfloat16* Bhi, const __nv_bfloat16* Blo,
    int bm, int bn, int k0, int K, int N, int tid)
{
    #pragma unroll
    for (int idx = tid; idx < 512; idx += 256) {
        const int r = idx >> 2, c = idx & 3;
        const uint32_t so = (uint32_t)(r * LDP * 2 + c * 16);
        const size_t ga = (size_t)(bm + r) * K + k0 + c * 8;
        cp16(sb + 0 * TILE_B + so, Ahi + ga);
        cp16(sb + 1 * TILE_B + so, Alo + ga);
        const bool v = (bn + r) < N;
        const size_t gb = v ? ((size_t)(bn + r) * K + k0 + c * 8) : 0;
        cp16_pred(sb + 2 * TILE_B + so, Bhi + gb, v);
        cp16_pred(sb + 3 * TILE_B + so, Blo + gb, v);
    }
}

__global__ __launch_bounds__(256, 2)
void gemm_mma(const __nv_bfloat16* __restrict__ Ahi, const __nv_bfloat16* __restrict__ Alo,
              const __nv_bfloat16* __restrict__ Bhi, const __nv_bfloat16* __restrict__ Blo,
              float* __restrict__ C, int N, int K, int ldc)
{
    extern __shared__ char smraw[];
    const uint32_t sbase = cvta_s(smraw);

    const int tid  = threadIdx.x;
    const int wid  = tid >> 5;
    const int lane = tid & 31;
    const int warp_m = (wid >> 2) * 64;
    const int warp_n = (wid & 3) * 32;
    const int bm = blockIdx.y * 128;
    const int bn = blockIdx.x * 128;
    const int nk = K / 32;

    float acc[4][4][4];
    #pragma unroll
    for (int i = 0; i < 4; ++i)
        #pragma unroll
        for (int j = 0; j < 4; ++j)
            #pragma unroll
            for (int q = 0; q < 4; ++q) acc[i][j][q] = 0.f;

    gload_stage(sbase, Ahi, Alo, Bhi, Blo, bm, bn, 0, K, N, tid);
    cp_commit();

    const int a_row = lane & 15;
    const int a_coff = (lane >> 4) << 3;
    const int b_row = lane & 7;
    const int b_coff = ((lane >> 3) & 1) << 3;

    for (int i = 0; i < nk; ++i) {
        if (i + 1 < nk) {
            gload_stage(sbase + ((i + 1) & 1) * STAGE_B, Ahi, Alo, Bhi, Blo,
                        bm, bn, (i + 1) * 32, K, N, tid);
            cp_commit();
            asm volatile("cp.async.wait_group 1;" ::: "memory");
        } else {
            asm volatile("cp.async.wait_group 0;" ::: "memory");
        }
        __syncthreads();

        const uint32_t sb = sbase + (i & 1) * STAGE_B;
        #pragma unroll
        for (int kc = 0; kc < 2; ++kc) {
            const int kel = kc * 16;
            uint32_t ah[4][4], al[4][4];
            #pragma unroll
            for (int mi = 0; mi < 4; ++mi) {
                const uint32_t ao = (uint32_t)((warp_m + mi * 16 + a_row) * LDP
                                               + kel + a_coff) * 2;
                ldm_x4(ah[mi], sb + ao);
                ldm_x4(al[mi], sb + TILE_B + ao);
            }
            #pragma unroll
            for (int ni = 0; ni < 4; ++ni) {
                const uint32_t bo = (uint32_t)((warp_n + ni * 8 + b_row) * LDP
                                               + kel + b_coff) * 2;
                uint32_t bh[2], bl[2];
                ldm_x2(bh[0], bh[1], sb + 2 * TILE_B + bo);
                ldm_x2(bl[0], bl[1], sb + 3 * TILE_B + bo);
                #pragma unroll
                for (int mi = 0; mi < 4; ++mi) {
                    mma_bf16(acc[mi][ni], ah[mi], bh);
                    mma_bf16(acc[mi][ni], ah[mi], bl);
                    mma_bf16(acc[mi][ni], al[mi], bh);
                }
            }
        }
        __syncthreads();
    }

    const int er = lane >> 2;
    const int ec = (lane & 3) * 2;
    #pragma unroll
    for (int mi = 0; mi < 4; ++mi) {
        #pragma unroll
        for (int ni = 0; ni < 4; ++ni) {
            const int col = bn + warp_n + ni * 8 + ec;
            if (col < N) {
                const int r0 = bm + warp_m + mi * 16 + er;
                *(float2*)(C + (size_t)r0 * ldc + col) =
                    make_float2(acc[mi][ni][0], acc[mi][ni][1]);
                *(float2*)(C + (size_t)(r0 + 8) * ldc + col) =
                    make_float2(acc[mi][ni][2], acc[mi][ni][3]);
            }
        }
    }
}

// ---------------------------------------------------------------------------
// fp32 -> (bf16 hi, bf16 lo) split kernels
// ---------------------------------------------------------------------------
union BV4 { __nv_bfloat16 b[4]; ushort4 u; };

__global__ void split_f32(const float* __restrict__ s, __nv_bfloat16* __restrict__ hi,
                          __nv_bfloat16* __restrict__ lo, int n4)
{
    const int i = blockIdx.x * blockDim.x + threadIdx.x;
    if (i >= n4) return;
    const float4 v = ((const float4*)s)[i];
    const float vv[4] = { v.x, v.y, v.z, v.w };
    BV4 H, L;
    #pragma unroll
    for (int j = 0; j < 4; ++j) {
        H.b[j] = __float2bfloat16(vv[j]);
        L.b[j] = __float2bfloat16(vv[j] - __bfloat162float(H.b[j]));
    }
    ((ushort4*)hi)[i] = H.u;
    ((ushort4*)lo)[i] = L.u;
}

__global__ void split_ckv(const float* __restrict__ s, __nv_bfloat16* __restrict__ hi,
                          __nv_bfloat16* __restrict__ lo)
{
    const int i = blockIdx.x * blockDim.x + threadIdx.x;
    const int r  = i >> 7;
    const int c4 = (i & 127) * 4;
    const float4 v = *(const float4*)(s + (size_t)r * 576 + c4);
    const float vv[4] = { v.x, v.y, v.z, v.w };
    BV4 H, L;
    #pragma unroll
    for (int j = 0; j < 4; ++j) {
        H.b[j] = __float2bfloat16(vv[j]);
        L.b[j] = __float2bfloat16(vv[j] - __bfloat162float(H.b[j]));
    }
    const size_t o = ((size_t)r * 512 + c4) / 4;
    ((ushort4*)hi)[o] = H.u;
    ((ushort4*)lo)[o] = L.u;
}

// ---------------------------------------------------------------------------
// Repack + RoPE -> bf16 hi/lo
// ---------------------------------------------------------------------------
__device__ __forceinline__ void wsplit(__nv_bfloat16* hi, __nv_bfloat16* lo,
                                       size_t idx, float v) {
    const __nv_bfloat16 h = __float2bfloat16(v);
    hi[idx] = h;
    lo[idx] = __float2bfloat16(v - __bfloat162float(h));
}

__global__ void build_q(const float* __restrict__ Q,
                        __nv_bfloat16* __restrict__ Qh, __nv_bfloat16* __restrict__ Ql)
{
    const int bs = blockIdx.x;
    const int b  = bs >> 11;
    const int s  = bs & 2047;
    const int h  = threadIdx.y;
    const int t  = threadIdx.x;

    const float* src = Q + (size_t)bs * (NHEAD * QK_D) + h * QK_D;
    const size_t dst = ((size_t)(b * NHEAD + h) * SLEN + s) * QK_D;

    wsplit(Qh, Ql, dst + t, src[t]);

    if (t < 32) {
        const float theta = powf(10000.f, -((float)(2 * t)) / 64.f);
        float sn, cs;
        sincosf((float)s * theta, &sn, &cs);
        const float x0 = src[64 + 2 * t];
        const float x1 = src[64 + 2 * t + 1];
        wsplit(Qh, Ql, dst + 64 + 2 * t,     x0 * cs - x1 * sn);
        wsplit(Qh, Ql, dst + 64 + 2 * t + 1, x1 * cs + x0 * sn);
    }
}

__global__ void build_k(const float* __restrict__ KVB, const float* __restrict__ CKV,
                        __nv_bfloat16* __restrict__ Kh, __nv_bfloat16* __restrict__ Kl)
{
    const int bs = blockIdx.x;
    const int b  = bs >> 11;
    const int s  = bs & 2047;
    const int h  = threadIdx.y;
    const int t  = threadIdx.x;

    const float* kv = KVB + (size_t)bs * 3072 + h * 192;
    const size_t dst = ((size_t)(b * NHEAD + h) * SLEN + s) * QK_D;

    wsplit(Kh, Kl, dst + t, kv[t]);

    if (t < 32) {
        const float theta = powf(10000.f, -((float)(2 * t)) / 64.f);
        float sn, cs;
        sincosf((float)s * theta, &sn, &cs);
        const float* kr = CKV + (size_t)bs * 576 + 512;
        const float x0 = kr[2 * t];
        const float x1 = kr[2 * t + 1];
        wsplit(Kh, Kl, dst + 64 + 2 * t,     x0 * cs - x1 * sn);
        wsplit(Kh, Kl, dst + 64 + 2 * t + 1, x1 * cs + x0 * sn);
    }
}

// V transpose: KVB[bs][h*192+64+d] -> Vt[bh][d][s]  (bf16 hi/lo)
__global__ void transpose_v(const float* __restrict__ KVB,
                            __nv_bfloat16* __restrict__ Vh, __nv_bfloat16* __restrict__ Vl)
{
    __shared__ float tile[64][132];
    const int bh = blockIdx.y;
    const int b  = bh >> 4;
    const int h  = bh & 15;
    const int s0 = blockIdx.x * 64;
    const int tid = threadIdx.x;

    #pragma unroll
    for (int p = 0; p < 8; ++p) {
        const int r = p * 8 + (tid >> 5);
        const int c = (tid & 31) * 4;
        const float4 v = *(const float4*)(KVB + (size_t)(b * SLEN + s0 + r) * 3072
                                          + h * 192 + 64 + c);
        tile[r][c + 0] = v.x;
        tile[r][c + 1] = v.y;
        tile[r][c + 2] = v.z;
        tile[r][c + 3] = v.w;
    }
    __syncthreads();

    const int d = tid >> 1;
    const int half = (tid & 1) * 32;
    const size_t obase = ((size_t)bh * 128 + d) * SLEN + s0 + half;
    #pragma unroll
    for (int j = 0; j < 32; j += 2) {
        const float v0 = tile[half + j][d];
        const float v1 = tile[half + j + 1][d];
        const float h0 = __bfloat162float(__float2bfloat16(v0));
        const float h1 = __bfloat162float(__float2bfloat16(v1));
        *(uint32_t*)(Vh + obase + j) = pack_bf2(v0, v1);
        *(uint32_t*)(Vl + obase + j) = pack_bf2(v0 - h0, v1 - h1);
    }
}

// ---------------------------------------------------------------------------
// Flash attention with split-bf16 HMMA.
// CTA: one (b,h) x 128 query rows; 8 warps x 16 rows. Key tiles of 64,
// double-buffered cp.async. Vt is [dim][seq].
// ---------------------------------------------------------------------------
#define QLDE 136               // Q/K smem row length (elements)
#define VLDE 72                // Vt smem row length
#define OFF_QH 0
#define OFF_QL 34816           // 128*136*2
#define OFF_STG 69632
#define STG_SZ 71680           // K hi/lo (2*17408) + Vt hi/lo (2*18432)
#define SOFF_KH 0
#define SOFF_KL 17408
#define SOFF_VH 34816
#define SOFF_VL 53248
#define FLASH_SMEM (OFF_STG + 2 * STG_SZ)   // 212992

__device__ __forceinline__ void fa_load_kv(
    uint32_t base, const __nv_bfloat16* Kh, const __nv_bfloat16* Kl,
    const __nv_bfloat16* Vh, const __nv_bfloat16* Vl,
    int bh, int kt, int tid)
{
    const size_t gk = ((size_t)bh * SLEN + kt * 64) * QK_D;
    #pragma unroll
    for (int i = tid; i < 1024; i += 256) {
        const int r = i >> 4, c = (i & 15) * 8;
        const uint32_t so = (uint32_t)(r * QLDE + c) * 2;
        cp16(base + SOFF_KH + so, Kh + gk + (size_t)r * QK_D + c);
        cp16(base + SOFF_KL + so, Kl + gk + (size_t)r * QK_D + c);
    }
    const size_t gv = (size_t)bh * V_D * SLEN + kt * 64;
    #pragma unroll
    for (int i = tid; i < 1024; i += 256) {
        const int r = i >> 3, c = (i & 7) * 8;
        const uint32_t so = (uint32_t)(r * VLDE + c) * 2;
        cp16(base + SOFF_VH + so, Vh + gv + (size_t)r * SLEN + c);
        cp16(base + SOFF_VL + so, Vl + gv + (size_t)r * SLEN + c);
    }
}

__global__ __launch_bounds__(256, 1)
void flash_mma(const __nv_bfloat16* __restrict__ Qh, const __nv_bfloat16* __restrict__ Ql,
               const __nv_bfloat16* __restrict__ Kh, const __nv_bfloat16* __restrict__ Kl,
               const __nv_bfloat16* __restrict__ Vh, const __nv_bfloat16* __restrict__ Vl,
               __nv_bfloat16* __restrict__ Ohi, __nv_bfloat16* __restrict__ Olo)
{
    extern __shared__ char smraw[];
    const uint32_t sb0 = cvta_s(smraw);

    const int tid  = threadIdx.x;
    const int wid  = tid >> 5;
    const int lane = tid & 31;
    const int bh = blockIdx.y;
    const int b  = bh >> 4;
    const int h  = bh & 15;
    const int q0 = blockIdx.x * 128;
    const int r_base = wid * 16;

    // ---- load Q tile + first KV stage ----
    const size_t gq = ((size_t)bh * SLEN + q0) * QK_D;
    #pragma unroll
    for (int i = tid; i < 2048; i += 256) {
        const int r = i >> 4, c = (i & 15) * 8;
        const uint32_t so = (uint32_t)(r * QLDE + c) * 2;
        cp16(sb0 + OFF_QH + so, Qh + gq + (size_t)r * QK_D + c);
        cp16(sb0 + OFF_QL + so, Ql + gq + (size_t)r * QK_D + c);
    }
    fa_load_kv(sb0 + OFF_STG, Kh, Kl, Vh, Vl, bh, 0, tid);
    cp_commit();
    asm volatile("cp.async.wait_group 0;" ::: "memory");
    __syncthreads();

    // ---- Q fragments (held in registers for whole kernel) ----
    uint32_t qfh[8][4], qfl[8][4];
    {
        const int ar = lane & 15;
        const int ac = ((lane >> 4) & 1) * 8;
        #pragma unroll
        for (int kf = 0; kf < 8; ++kf) {
            const uint32_t off = (uint32_t)((r_base + ar) * QLDE + kf * 16 + ac) * 2;
            ldm_x4(qfh[kf], sb0 + OFF_QH + off);
            ldm_x4(qfl[kf], sb0 + OFF_QL + off);
        }
    }

    float Oa[16][4];
    #pragma unroll
    for (int i = 0; i < 16; ++i)
        #pragma unroll
        for (int j = 0; j < 4; ++j) Oa[i][j] = 0.f;
    float m0 = -INFINITY, m1 = -INFINITY, l0 = 0.f, l1 = 0.f;

    const int krow = lane & 7;
    const int kcol = ((lane >> 3) & 3) * 8;

    for (int kt = 0; kt < SLEN / 64; ++kt) {
        if (kt + 1 < SLEN / 64) {
            fa_load_kv(sb0 + OFF_STG + ((kt + 1) & 1) * STG_SZ,
                       Kh, Kl, Vh, Vl, bh, kt + 1, tid);
            cp_commit();
            asm volatile("cp.async.wait_group 1;" ::: "memory");
        } else {
            asm volatile("cp.async.wait_group 0;" ::: "memory");
        }
        __syncthreads();

        const uint32_t sk = sb0 + OFF_STG + (kt & 1) * STG_SZ;

        // ---- S = Q K^T (3-term split) ----
        float S[8][4];
        #pragma unroll
        for (int i = 0; i < 8; ++i)
            #pragma unroll
            for (int j = 0; j < 4; ++j) S[i][j] = 0.f;

        #pragma unroll
        for (int nb = 0; nb < 8; ++nb) {
            #pragma unroll
            for (int kfp = 0; kfp < 4; ++kfp) {
                const uint32_t ko = (uint32_t)((nb * 8 + krow) * QLDE
                                               + kfp * 32 + kcol) * 2;
                uint32_t kfh[4], kfl[4];
                ldm_x4(kfh, sk + SOFF_KH + ko);
                ldm_x4(kfl, sk + SOFF_KL + ko);
                mma_bf16(S[nb], qfh[2 * kfp],     kfh);
                mma_bf16(S[nb], qfh[2 * kfp + 1], kfh + 2);
                mma_bf16(S[nb], qfl[2 * kfp],     kfh);
                mma_bf16(S[nb], qfl[2 * kfp + 1], kfh + 2);
                mma_bf16(S[nb], qfh[2 * kfp],     kfl);
                mma_bf16(S[nb], qfh[2 * kfp + 1], kfl + 2);
            }
        }

        // ---- online softmax ----
        float mx0 = -INFINITY, mx1 = -INFINITY;
        #pragma unroll
        for (int nb = 0; nb < 8; ++nb) {
            mx0 = fmaxf(mx0, fmaxf(S[nb][0], S[nb][1]));
            mx1 = fmaxf(mx1, fmaxf(S[nb][2], S[nb][3]));
        }
        mx0 = fmaxf(mx0, __shfl_xor_sync(0xffffffffu, mx0, 1));
        mx0 = fmaxf(mx0, __shfl_xor_sync(0xffffffffu, mx0, 2));
        mx1 = fmaxf(mx1, __shfl_xor_sync(0xffffffffu, mx1, 1));
        mx1 = fmaxf(mx1, __shfl_xor_sync(0xffffffffu, mx1, 2));

        const float mn0 = fmaxf(m0, mx0);
        const float mn1 = fmaxf(m1, mx1);
        const float f0 = __expf(m0 - mn0);
        const float f1 = __expf(m1 - mn1);
        m0 = mn0; m1 = mn1;

        float rs0 = 0.f, rs1 = 0.f;
        #pragma unroll
        for (int nb = 0; nb < 8; ++nb) {
            S[nb][0] = __expf(S[nb][0] - mn0);
            S[nb][1] = __expf(S[nb][1] - mn0);
            S[nb][2] = __expf(S[nb][2] - mn1);
            S[nb][3] = __expf(S[nb][3] - mn1);
            rs0 += S[nb][0] + S[nb][1];
            rs1 += S[nb][2] + S[nb][3];
        }
        rs0 += __shfl_xor_sync(0xffffffffu, rs0, 1);
        rs0 += __shfl_xor_sync(0xffffffffu, rs0, 2);
        rs1 += __shfl_xor_sync(0xffffffffu, rs1, 1);
        rs1 += __shfl_xor_sync(0xffffffffu, rs1, 2);
        l0 = l0 * f0 + rs0;
        l1 = l1 * f1 + rs1;

        #pragma unroll
        for (int i = 0; i < 16; ++i) {
            Oa[i][0] *= f0; Oa[i][1] *= f0;
            Oa[i][2] *= f1; Oa[i][3] *= f1;
        }

        // ---- pack P into A fragments (hi + residual lo) ----
        uint32_t ph[4][4], pl[4][4];
        #pragma unroll
        for (int kf2 = 0; kf2 < 4; ++kf2) {
            const float* s0p = S[2 * kf2];
            const float* s1p = S[2 * kf2 + 1];
            ph[kf2][0] = pack_bf2(s0p[0], s0p[1]);
            ph[kf2][1] = pack_bf2(s0p[2], s0p[3]);
            ph[kf2][2] = pack_bf2(s1p[0], s1p[1]);
            ph[kf2][3] = pack_bf2(s1p[2], s1p[3]);
            pl[kf2][0] = pack_bf2(bf_res(s0p[0]), bf_res(s0p[1]));
            pl[kf2][1] = pack_bf2(bf_res(s0p[2]), bf_res(s0p[3]));
            pl[kf2][2] = pack_bf2(bf_res(s1p[0]), bf_res(s1p[1]));
            pl[kf2][3] = pack_bf2(bf_res(s1p[2]), bf_res(s1p[3]));
        }

        // ---- O += P V  (3-term split; Vt is [dim][seq]) ----
        #pragma unroll
        for (int nb2 = 0; nb2 < 16; ++nb2) {
            #pragma unroll
            for (int kfp2 = 0; kfp2 < 2; ++kfp2) {
                const uint32_t vo = (uint32_t)((nb2 * 8 + krow) * VLDE
                                               + kfp2 * 32 + kcol) * 2;
                uint32_t vfh[4], vfl[4];
                ldm_x4(vfh, sk + SOFF_VH + vo);
                ldm_x4(vfl, sk + SOFF_VL + vo);
                mma_bf16(Oa[nb2], ph[2 * kfp2],     vfh);
                mma_bf16(Oa[nb2], ph[2 * kfp2 + 1], vfh + 2);
                mma_bf16(Oa[nb2], pl[2 * kfp2],     vfh);
                mma_bf16(Oa[nb2], pl[2 * kfp2 + 1], vfh + 2);
                mma_bf16(Oa[nb2], ph[2 * kfp2],     vfl);
                mma_bf16(Oa[nb2], ph[2 * kfp2 + 1], vfl + 2);
            }
        }
        __syncthreads();
    }

    // ---- epilogue: O/l -> bf16 hi/lo ----
    const float inv0 = 1.f / l0;
    const float inv1 = 1.f / l1;
    const int er = lane >> 2;
    const int ec = (lane & 3) * 2;
    const size_t row0 = (size_t)(b * SLEN + q0 + r_base + er) * (NHEAD * V_D) + h * V_D;
    const size_t row1 = row0 + (size_t)8 * (NHEAD * V_D);
    #pragma unroll
    for (int nb2 = 0; nb2 < 16; ++nb2) {
        const int col = nb2 * 8 + ec;
        const float a0 = Oa[nb2][0] * inv0, a1 = Oa[nb2][1] * inv0;
        const float a2 = Oa[nb2][2] * inv1, a3 = Oa[nb2][3] * inv1;
        *(uint32_t*)(Ohi + row0 + col) = pack_bf2(a0, a1);
        *(uint32_t*)(Olo + row0 + col) = pack_bf2(bf_res(a0), bf_res(a1));
        *(uint32_t*)(Ohi + row1 + col) = pack_bf2(a2, a3);
        *(uint32_t*)(Olo + row1 + col) = pack_bf2(bf_res(a2), bf_res(a3));
    }
}

// ---------------------------------------------------------------------------
extern "C" void kernel_launch(void* const* d_in, const int* in_sizes, int n_in,
                              void* d_out, int out_size)
{
    const float* x    = (const float*)d_in[0];
    const float* q_a  = (const float*)d_in[1];
    const float* q_b  = (const float*)d_in[2];
    const float* kv_a = (const float*)d_in[3];
    const float* kv_b = (const float*)d_in[4];
    const float* o_w  = (const float*)d_in[5];
    float* out = (float*)d_out;

    float *Xq, *Q, *CKV, *KVB;
    cudaGetSymbolAddress((void**)&Xq,  g_Xq);
    cudaGetSymbolAddress((void**)&Q,   g_Q);
    cudaGetSymbolAddress((void**)&CKV, g_CKV);
    cudaGetSymbolAddress((void**)&KVB, g_KVB);

    __nv_bfloat16 *x_hi, *x_lo, *qa_hi, *qa_lo, *qb_hi, *qb_lo, *kva_hi, *kva_lo;
    __nv_bfloat16 *kvb_hi, *kvb_lo, *ow_hi, *ow_lo, *Xq_hi, *Xq_lo, *ckv_hi, *ckv_lo;
    __nv_bfloat16 *Qb_hi, *Qb_lo, *Kb_hi, *Kb_lo, *Vt_hi, *Vt_lo, *O_hi, *O_lo;
    cudaGetSymbolAddress((void**)&x_hi,   g_x_hi);
    cudaGetSymbolAddress((void**)&x_lo,   g_x_lo);
    cudaGetSymbolAddress((void**)&qa_hi,  g_qa_hi);
    cudaGetSymbolAddress((void**)&qa_lo,  g_qa_lo);
    cudaGetSymbolAddress((void**)&qb_hi,  g_qb_hi);
    cudaGetSymbolAddress((void**)&qb_lo,  g_qb_lo);
    cudaGetSymbolAddress((void**)&kva_hi, g_kva_hi);
    cudaGetSymbolAddress((void**)&kva_lo, g_kva_lo);
    cudaGetSymbolAddress((void**)&kvb_hi, g_kvb_hi);
    cudaGetSymbolAddress((void**)&kvb_lo, g_kvb_lo);
    cudaGetSymbolAddress((void**)&ow_hi,  g_ow_hi);
    cudaGetSymbolAddress((void**)&ow_lo,  g_ow_lo);
    cudaGetSymbolAddress((void**)&Xq_hi,  g_Xq_hi);
    cudaGetSymbolAddress((void**)&Xq_lo,  g_Xq_lo);
    cudaGetSymbolAddress((void**)&ckv_hi, g_ckv_hi);
    cudaGetSymbolAddress((void**)&ckv_lo, g_ckv_lo);
    cudaGetSymbolAddress((void**)&Qb_hi,  g_Qb_hi);
    cudaGetSymbolAddress((void**)&Qb_lo,  g_Qb_lo);
    cudaGetSymbolAddress((void**)&Kb_hi,  g_Kb_hi);
    cudaGetSymbolAddress((void**)&Kb_lo,  g_Kb_lo);
    cudaGetSymbolAddress((void**)&Vt_hi,  g_Vt_hi);
    cudaGetSymbolAddress((void**)&Vt_lo,  g_Vt_lo);
    cudaGetSymbolAddress((void**)&O_hi,   g_O_hi);
    cudaGetSymbolAddress((void**)&O_lo,   g_O_lo);

    cudaFuncSetAttribute(gemm_mma, cudaFuncAttributeMaxDynamicSharedMemorySize,
                         GEMM_SMEM);
    cudaFuncSetAttribute(flash_mma, cudaFuncAttributeMaxDynamicSharedMemorySize,
                         FLASH_SMEM);

    const int TPB = 256;
    #define SPLIT(src, hi, lo, n) \
        split_f32<<<((n) / 4 + TPB - 1) / TPB, TPB>>>(src, hi, lo, (n) / 4)

    SPLIT(x,    x_hi,   x_lo,   MROWS * EMB);
    SPLIT(q_a,  qa_hi,  qa_lo,  QRANK * EMB);
    SPLIT(q_b,  qb_hi,  qb_lo,  (NHEAD * QK_D) * QRANK);
    SPLIT(kv_a, kva_hi, kva_lo, 576 * EMB);
    SPLIT(kv_b, kvb_hi, kvb_lo, 3072 * KVRANK);
    SPLIT(o_w,  ow_hi,  ow_lo,  EMB * (NHEAD * V_D));

    // 1) Xq = x @ q_a^T
    gemm_mma<<<dim3(12, 32), 256, GEMM_SMEM>>>(x_hi, x_lo, qa_hi, qa_lo,
                                               Xq, QRANK, EMB, QRANK);
    SPLIT(Xq, Xq_hi, Xq_lo, MROWS * QRANK);
    // 2) Q = Xq @ q_b^T
    gemm_mma<<<dim3(16, 32), 256, GEMM_SMEM>>>(Xq_hi, Xq_lo, qb_hi, qb_lo,
                                               Q, NHEAD * QK_D, QRANK, NHEAD * QK_D);
    // 3) CKV = x @ kv_a^T
    gemm_mma<<<dim3(5, 32), 256, GEMM_SMEM>>>(x_hi, x_lo, kva_hi, kva_lo,
                                              CKV, 576, EMB, 576);
    split_ckv<<<(MROWS * 128) / TPB, TPB>>>(CKV, ckv_hi, ckv_lo);
    // 4) KVB = CKV512 @ kv_b^T
    gemm_mma<<<dim3(24, 32), 256, GEMM_SMEM>>>(ckv_hi, ckv_lo, kvb_hi, kvb_lo,
                                               KVB, 3072, KVRANK, 3072);
    // 5) repack (rope) to bf16 hi/lo + V transpose
    build_q<<<MROWS, dim3(64, NHEAD)>>>(Q, Qb_hi, Qb_lo);
    build_k<<<MROWS, dim3(64, NHEAD)>>>(KVB, CKV, Kb_hi, Kb_lo);
    transpose_v<<<dim3(SLEN / 64, BHN), 256>>>(KVB, Vt_hi, Vt_lo);
    // 6) attention (HMMA)
    flash_mma<<<dim3(SLEN / 128, BHN), 256, FLASH_SMEM>>>(
        Qb_hi, Qb_lo, Kb_hi, Kb_lo, Vt_hi, Vt_lo, O_hi, O_lo);
    // 7) out = O @ o_w^T
    gemm_mma<<<dim3(16, 32), 256, GEMM_SMEM>>>(O_hi, O_lo, ow_hi, ow_lo,
                                               out, EMB, NHEAD * V_D, EMB);
    #undef SPLIT
}

// round 5
// speedup vs baseline: 3.8955x; 1.0497x over previous
#include <cuda_runtime.h>
#include <cuda_bf16.h>
#include <math.h>
#include <stdint.h>

// ---------------------------------------------------------------------------
// Problem constants
// ---------------------------------------------------------------------------
#define BATCH   2
#define SLEN    2048
#define EMB     2048
#define NHEAD   16
#define QRANK   1536
#define KVRANK  512
#define QK_D    128
#define V_D     128
#define MROWS   (BATCH * SLEN)        // 4096
#define BHN     (BATCH * NHEAD)       // 32
#define NXC     (QRANK + 576)         // 2112 merged x-GEMM output width

// ------------------------- fp32 scratch -----------------------------------
__device__ float g_XC [(size_t)MROWS * NXC];            // [Xq | CKV]
__device__ float g_Q  [(size_t)MROWS * (NHEAD * QK_D)];
__device__ float g_KVB[(size_t)MROWS * 3072];

// ------------------------- bf16 hi/lo split buffers -----------------------
__device__ __nv_bfloat16 g_x_hi   [(size_t)MROWS * EMB];
__device__ __nv_bfloat16 g_x_lo   [(size_t)MROWS * EMB];
__device__ __nv_bfloat16 g_qakva_hi[(size_t)NXC * EMB];   // rows 0..1535 = q_a, 1536.. = kv_a
__device__ __nv_bfloat16 g_qakva_lo[(size_t)NXC * EMB];
__device__ __nv_bfloat16 g_qb_hi  [(size_t)(NHEAD * QK_D) * QRANK];
__device__ __nv_bfloat16 g_qb_lo  [(size_t)(NHEAD * QK_D) * QRANK];
__device__ __nv_bfloat16 g_kvb_hi [(size_t)3072 * KVRANK];
__device__ __nv_bfloat16 g_kvb_lo [(size_t)3072 * KVRANK];
__device__ __nv_bfloat16 g_ow_hi  [(size_t)EMB * (NHEAD * V_D)];
__device__ __nv_bfloat16 g_ow_lo  [(size_t)EMB * (NHEAD * V_D)];
__device__ __nv_bfloat16 g_XC_hi  [(size_t)MROWS * NXC];
__device__ __nv_bfloat16 g_XC_lo  [(size_t)MROWS * NXC];
// attention operands / results (bf16 hi/lo)
__device__ __nv_bfloat16 g_Qb_hi [(size_t)BHN * SLEN * QK_D];
__device__ __nv_bfloat16 g_Qb_lo [(size_t)BHN * SLEN * QK_D];
__device__ __nv_bfloat16 g_Kb_hi [(size_t)BHN * SLEN * QK_D];
__device__ __nv_bfloat16 g_Kb_lo [(size_t)BHN * SLEN * QK_D];
__device__ __nv_bfloat16 g_Vt_hi [(size_t)BHN * V_D * SLEN];
__device__ __nv_bfloat16 g_Vt_lo [(size_t)BHN * V_D * SLEN];
__device__ __nv_bfloat16 g_O_hi  [(size_t)MROWS * (NHEAD * V_D)];
__device__ __nv_bfloat16 g_O_lo  [(size_t)MROWS * (NHEAD * V_D)];

// ---------------------------------------------------------------------------
// PTX helpers (arch-agnostic, legal at compute_103)
// ---------------------------------------------------------------------------
__device__ __forceinline__ uint32_t cvta_s(const void* p) {
    return (uint32_t)__cvta_generic_to_shared(p);
}
__device__ __forceinline__ void cp16(uint32_t dst, const void* src) {
    asm volatile("cp.async.cg.shared.global [%0], [%1], 16;"
                 :: "r"(dst), "l"(src) : "memory");
}
__device__ __forceinline__ void cp16_pred(uint32_t dst, const void* src, bool valid) {
    const int sz = valid ? 16 : 0;
    asm volatile("cp.async.cg.shared.global [%0], [%1], 16, %2;"
                 :: "r"(dst), "l"(src), "r"(sz) : "memory");
}
__device__ __forceinline__ void cp_commit() {
    asm volatile("cp.async.commit_group;" ::: "memory");
}
__device__ __forceinline__ void ldm_x4(uint32_t* r, uint32_t addr) {
    asm volatile("ldmatrix.sync.aligned.m8n8.x4.shared.b16 {%0,%1,%2,%3}, [%4];"
                 : "=r"(r[0]), "=r"(r[1]), "=r"(r[2]), "=r"(r[3]) : "r"(addr));
}
__device__ __forceinline__ void ldm_x2(uint32_t& r0, uint32_t& r1, uint32_t addr) {
    asm volatile("ldmatrix.sync.aligned.m8n8.x2.shared.b16 {%0,%1}, [%2];"
                 : "=r"(r0), "=r"(r1) : "r"(addr));
}
__device__ __forceinline__ void mma_bf16(float* c, const uint32_t* a,
                                         const uint32_t* b) {
    asm volatile(
        "mma.sync.aligned.m16n8k16.row.col.f32.bf16.bf16.f32 "
        "{%0,%1,%2,%3}, {%4,%5,%6,%7}, {%8,%9}, {%0,%1,%2,%3};"
        : "+f"(c[0]), "+f"(c[1]), "+f"(c[2]), "+f"(c[3])
        : "r"(a[0]), "r"(a[1]), "r"(a[2]), "r"(a[3]), "r"(b[0]), "r"(b[1]));
}
__device__ __forceinline__ uint32_t pack_bf2(float lo, float hi) {
    uint32_t r;
    asm("cvt.rn.bf16x2.f32 %0, %1, %2;" : "=r"(r) : "f"(hi), "f"(lo));
    return r;
}
__device__ __forceinline__ float bf_res(float v) {
    return v - __bfloat162float(__float2bfloat16(v));
}

// ---------------------------------------------------------------------------
// HMMA split-bf16 GEMM body (NT): C[M,N] = A[M,K] @ B[N,K]^T
// CTA tile 128x128, BK=32, 8 warps, warp tile 64x32.
// Optional fp32 output C and/or bf16 hi/lo outputs Chi/Clo.
// ---------------------------------------------------------------------------
#define LDP 40
#define TILE_B (128 * LDP * 2)
#define STAGE_B (4 * TILE_B)
#define GEMM_SMEM (2 * STAGE_B)

__device__ __forceinline__ void gload_stage(
    uint32_t sb, const __nv_bfloat16* Ahi, const __nv_bfloat16* Alo, int lda,
    const __nv_bfloat16* Bhi, const __nv_bfloat16* Blo,
    int bm, int bn, int k0, int K, int N, int tid)
{
    #pragma unroll
    for (int idx = tid; idx < 512; idx += 256) {
        const int r = idx >> 2, c = idx & 3;
        const uint32_t so = (uint32_t)(r * LDP * 2 + c * 16);
        const size_t ga = (size_t)(bm + r) * lda + k0 + c * 8;
        cp16(sb + 0 * TILE_B + so, Ahi + ga);
        cp16(sb + 1 * TILE_B + so, Alo + ga);
        const bool v = (bn + r) < N;
        const size_t gb = v ? ((size_t)(bn + r) * K + k0 + c * 8) : 0;
        cp16_pred(sb + 2 * TILE_B + so, Bhi + gb, v);
        cp16_pred(sb + 3 * TILE_B + so, Blo + gb, v);
    }
}

__device__ __forceinline__ void gemm_body(
    uint32_t sbase,
    const __nv_bfloat16* __restrict__ Ahi, const __nv_bfloat16* __restrict__ Alo,
    int lda,
    const __nv_bfloat16* __restrict__ Bhi, const __nv_bfloat16* __restrict__ Blo,
    float* __restrict__ C, __nv_bfloat16* __restrict__ Chi,
    __nv_bfloat16* __restrict__ Clo,
    int N, int K, int ldc, int bm, int bn)
{
    const int tid  = threadIdx.x;
    const int wid  = tid >> 5;
    const int lane = tid & 31;
    const int warp_m = (wid >> 2) * 64;
    const int warp_n = (wid & 3) * 32;
    const int nk = K / 32;

    float acc[4][4][4];
    #pragma unroll
    for (int i = 0; i < 4; ++i)
        #pragma unroll
        for (int j = 0; j < 4; ++j)
            #pragma unroll
            for (int q = 0; q < 4; ++q) acc[i][j][q] = 0.f;

    gload_stage(sbase, Ahi, Alo, lda, Bhi, Blo, bm, bn, 0, K, N, tid);
    cp_commit();

    const int a_row = lane & 15;
    const int a_coff = (lane >> 4) << 3;
    const int b_row = lane & 7;
    const int b_coff = ((lane >> 3) & 1) << 3;

    for (int i = 0; i < nk; ++i) {
        if (i + 1 < nk) {
            gload_stage(sbase + ((i + 1) & 1) * STAGE_B, Ahi, Alo, lda, Bhi, Blo,
                        bm, bn, (i + 1) * 32, K, N, tid);
            cp_commit();
            asm volatile("cp.async.wait_group 1;" ::: "memory");
        } else {
            asm volatile("cp.async.wait_group 0;" ::: "memory");
        }
        __syncthreads();

        const uint32_t sb = sbase + (i & 1) * STAGE_B;
        #pragma unroll
        for (int kc = 0; kc < 2; ++kc) {
            const int kel = kc * 16;
            uint32_t ah[4][4], al[4][4];
            #pragma unroll
            for (int mi = 0; mi < 4; ++mi) {
                const uint32_t ao = (uint32_t)((warp_m + mi * 16 + a_row) * LDP
                                               + kel + a_coff) * 2;
                ldm_x4(ah[mi], sb + ao);
                ldm_x4(al[mi], sb + TILE_B + ao);
            }
            #pragma unroll
            for (int ni = 0; ni < 4; ++ni) {
                const uint32_t bo = (uint32_t)((warp_n + ni * 8 + b_row) * LDP
                                               + kel + b_coff) * 2;
                uint32_t bh[2], bl[2];
                ldm_x2(bh[0], bh[1], sb + 2 * TILE_B + bo);
                ldm_x2(bl[0], bl[1], sb + 3 * TILE_B + bo);
                #pragma unroll
                for (int mi = 0; mi < 4; ++mi) {
                    mma_bf16(acc[mi][ni], ah[mi], bh);
                    mma_bf16(acc[mi][ni], ah[mi], bl);
                    mma_bf16(acc[mi][ni], al[mi], bh);
                }
            }
        }
        __syncthreads();
    }

    const int er = lane >> 2;
    const int ec = (lane & 3) * 2;
    #pragma unroll
    for (int mi = 0; mi < 4; ++mi) {
        #pragma unroll
        for (int ni = 0; ni < 4; ++ni) {
            const int col = bn + warp_n + ni * 8 + ec;
            if (col < N) {
                const int r0 = bm + warp_m + mi * 16 + er;
                const float a0 = acc[mi][ni][0], a1 = acc[mi][ni][1];
                const float a2 = acc[mi][ni][2], a3 = acc[mi][ni][3];
                if (C) {
                    *(float2*)(C + (size_t)r0 * ldc + col) = make_float2(a0, a1);
                    *(float2*)(C + (size_t)(r0 + 8) * ldc + col) = make_float2(a2, a3);
                }
                if (Chi) {
                    *(uint32_t*)(Chi + (size_t)r0 * ldc + col) = pack_bf2(a0, a1);
                    *(uint32_t*)(Clo + (size_t)r0 * ldc + col) =
                        pack_bf2(bf_res(a0), bf_res(a1));
                    *(uint32_t*)(Chi + (size_t)(r0 + 8) * ldc + col) = pack_bf2(a2, a3);
                    *(uint32_t*)(Clo + (size_t)(r0 + 8) * ldc + col) =
                        pack_bf2(bf_res(a2), bf_res(a3));
                }
            }
        }
    }
}

__global__ __launch_bounds__(256, 2)
void gemm_one(const __nv_bfloat16* __restrict__ Ahi, const __nv_bfloat16* __restrict__ Alo,
              int lda,
              const __nv_bfloat16* __restrict__ Bhi, const __nv_bfloat16* __restrict__ Blo,
              float* __restrict__ C, __nv_bfloat16* __restrict__ Chi,
              __nv_bfloat16* __restrict__ Clo, int N, int K, int ldc)
{
    extern __shared__ char smraw[];
    gemm_body(cvta_s(smraw), Ahi, Alo, lda, Bhi, Blo, C, Chi, Clo,
              N, K, ldc, blockIdx.y * 128, blockIdx.x * 128);
}

// two independent GEMMs in one launch (block-decoded)
__global__ __launch_bounds__(256, 2)
void gemm_two(const __nv_bfloat16* A1h, const __nv_bfloat16* A1l, int lda1,
              const __nv_bfloat16* B1h, const __nv_bfloat16* B1l,
              float* C1, int N1, int K1, int ldc1,
              const __nv_bfloat16* A2h, const __nv_bfloat16* A2l, int lda2,
              const __nv_bfloat16* B2h, const __nv_bfloat16* B2l,
              float* C2, int N2, int K2, int ldc2, int bx_split)
{
    extern __shared__ char smraw[];
    const uint32_t sb = cvta_s(smraw);
    if ((int)blockIdx.x < bx_split)
        gemm_body(sb, A1h, A1l, lda1, B1h, B1l, C1, nullptr, nullptr,
                  N1, K1, ldc1, blockIdx.y * 128, blockIdx.x * 128);
    else
        gemm_body(sb, A2h, A2l, lda2, B2h, B2l, C2, nullptr, nullptr,
                  N2, K2, ldc2, blockIdx.y * 128, (blockIdx.x - bx_split) * 128);
}

// ---------------------------------------------------------------------------
// Grouped fp32 -> (bf16 hi, bf16 lo) split: all 6 inputs in one launch.
// Segment sizes are compile-time constants (vec4 units).
// ---------------------------------------------------------------------------
union BV4 { __nv_bfloat16 b[4]; ushort4 u; };

#define NV4_X   (MROWS * EMB / 4)                 // 2097152
#define NV4_QA  (QRANK * EMB / 4)                 //  786432
#define NV4_KVA (576 * EMB / 4)                   //  294912
#define NV4_QB  ((NHEAD * QK_D) * QRANK / 4)      //  786432
#define NV4_KVB (3072 * KVRANK / 4)               //  393216
#define NV4_OW  (EMB * (NHEAD * V_D) / 4)         // 1048576
#define C1_ (NV4_X)
#define C2_ (C1_ + NV4_QA)
#define C3_ (C2_ + NV4_KVA)
#define C4_ (C3_ + NV4_QB)
#define C5_ (C4_ + NV4_KVB)
#define C6_ (C5_ + NV4_OW)
#define SPLIT_BLOCKS ((C6_ + 255) / 256)

__global__ void split_all(const float* __restrict__ x,  const float* __restrict__ qa,
                          const float* __restrict__ kva, const float* __restrict__ qb,
                          const float* __restrict__ kvb, const float* __restrict__ ow,
                          __nv_bfloat16* __restrict__ xh,   __nv_bfloat16* __restrict__ xl,
                          __nv_bfloat16* __restrict__ qkh,  __nv_bfloat16* __restrict__ qkl,
                          __nv_bfloat16* __restrict__ qbh,  __nv_bfloat16* __restrict__ qbl,
                          __nv_bfloat16* __restrict__ kvbh, __nv_bfloat16* __restrict__ kvbl,
                          __nv_bfloat16* __restrict__ owh,  __nv_bfloat16* __restrict__ owl)
{
    const int i = blockIdx.x * blockDim.x + threadIdx.x;
    if (i >= C6_) return;

    const float* src; __nv_bfloat16 *hi, *lo; int o;
    if (i < C1_)      { src = x;   hi = xh;   lo = xl;   o = i; }
    else if (i < C2_) { src = qa;  hi = qkh;  lo = qkl;  o = i - C1_; }
    else if (i < C3_) { src = kva; hi = qkh + (size_t)QRANK * EMB;
                        lo = qkl + (size_t)QRANK * EMB;  o = i - C2_; }
    else if (i < C4_) { src = qb;  hi = qbh;  lo = qbl;  o = i - C3_; }
    else if (i < C5_) { src = kvb; hi = kvbh; lo = kvbl; o = i - C4_; }
    else              { src = ow;  hi = owh;  lo = owl;  o = i - C5_; }

    const float4 v = ((const float4*)src)[o];
    const float vv[4] = { v.x, v.y, v.z, v.w };
    BV4 H, L;
    #pragma unroll
    for (int j = 0; j < 4; ++j) {
        H.b[j] = __float2bfloat16(vv[j]);
        L.b[j] = __float2bfloat16(vv[j] - __bfloat162float(H.b[j]));
    }
    ((ushort4*)hi)[o] = H.u;
    ((ushort4*)lo)[o] = L.u;
}

// ---------------------------------------------------------------------------
// Repack + RoPE -> bf16 hi/lo
// ---------------------------------------------------------------------------
__device__ __forceinline__ void wsplit(__nv_bfloat16* hi, __nv_bfloat16* lo,
                                       size_t idx, float v) {
    const __nv_bfloat16 h = __float2bfloat16(v);
    hi[idx] = h;
    lo[idx] = __float2bfloat16(v - __bfloat162float(h));
}

__global__ void build_q(const float* __restrict__ Q,
                        __nv_bfloat16* __restrict__ Qh, __nv_bfloat16* __restrict__ Ql)
{
    const int bs = blockIdx.x;
    const int b  = bs >> 11;
    const int s  = bs & 2047;
    const int h  = threadIdx.y;
    const int t  = threadIdx.x;

    const float* src = Q + (size_t)bs * (NHEAD * QK_D) + h * QK_D;
    const size_t dst = ((size_t)(b * NHEAD + h) * SLEN + s) * QK_D;

    wsplit(Qh, Ql, dst + t, src[t]);

    if (t < 32) {
        const float theta = powf(10000.f, -((float)(2 * t)) / 64.f);
        float sn, cs;
        sincosf((float)s * theta, &sn, &cs);
        const float x0 = src[64 + 2 * t];
        const float x1 = src[64 + 2 * t + 1];
        wsplit(Qh, Ql, dst + 64 + 2 * t,     x0 * cs - x1 * sn);
        wsplit(Qh, Ql, dst + 64 + 2 * t + 1, x1 * cs + x0 * sn);
    }
}

// k_rot now comes from g_XC columns [2048, 2112)
__global__ void build_k(const float* __restrict__ KVB, const float* __restrict__ XC,
                        __nv_bfloat16* __restrict__ Kh, __nv_bfloat16* __restrict__ Kl)
{
    const int bs = blockIdx.x;
    const int b  = bs >> 11;
    const int s  = bs & 2047;
    const int h  = threadIdx.y;
    const int t  = threadIdx.x;

    const float* kv = KVB + (size_t)bs * 3072 + h * 192;
    const size_t dst = ((size_t)(b * NHEAD + h) * SLEN + s) * QK_D;

    wsplit(Kh, Kl, dst + t, kv[t]);

    if (t < 32) {
        const float theta = powf(10000.f, -((float)(2 * t)) / 64.f);
        float sn, cs;
        sincosf((float)s * theta, &sn, &cs);
        const float* kr = XC + (size_t)bs * NXC + 2048;
        const float x0 = kr[2 * t];
        const float x1 = kr[2 * t + 1];
        wsplit(Kh, Kl, dst + 64 + 2 * t,     x0 * cs - x1 * sn);
        wsplit(Kh, Kl, dst + 64 + 2 * t + 1, x1 * cs + x0 * sn);
    }
}

// V transpose: KVB[bs][h*192+64+d] -> Vt[bh][d][s]  (bf16 hi/lo)
__global__ void transpose_v(const float* __restrict__ KVB,
                            __nv_bfloat16* __restrict__ Vh, __nv_bfloat16* __restrict__ Vl)
{
    __shared__ float tile[64][132];
    const int bh = blockIdx.y;
    const int b  = bh >> 4;
    const int h  = bh & 15;
    const int s0 = blockIdx.x * 64;
    const int tid = threadIdx.x;

    #pragma unroll
    for (int p = 0; p < 8; ++p) {
        const int r = p * 8 + (tid >> 5);
        const int c = (tid & 31) * 4;
        const float4 v = *(const float4*)(KVB + (size_t)(b * SLEN + s0 + r) * 3072
                                          + h * 192 + 64 + c);
        tile[r][c + 0] = v.x;
        tile[r][c + 1] = v.y;
        tile[r][c + 2] = v.z;
        tile[r][c + 3] = v.w;
    }
    __syncthreads();

    const int d = tid >> 1;
    const int half = (tid & 1) * 32;
    const size_t obase = ((size_t)bh * 128 + d) * SLEN + s0 + half;
    #pragma unroll
    for (int j = 0; j < 32; j += 2) {
        const float v0 = tile[half + j][d];
        const float v1 = tile[half + j + 1][d];
        const float h0 = __bfloat162float(__float2bfloat16(v0));
        const float h1 = __bfloat162float(__float2bfloat16(v1));
        *(uint32_t*)(Vh + obase + j) = pack_bf2(v0, v1);
        *(uint32_t*)(Vl + obase + j) = pack_bf2(v0 - h0, v1 - h1);
    }
}

// ---------------------------------------------------------------------------
// Flash attention with split-bf16 HMMA (unchanged from round 4)
// ---------------------------------------------------------------------------
#define QLDE 136
#define VLDE 72
#define OFF_QH 0
#define OFF_QL 34816
#define OFF_STG 69632
#define STG_SZ 71680
#define SOFF_KH 0
#define SOFF_KL 17408
#define SOFF_VH 34816
#define SOFF_VL 53248
#define FLASH_SMEM (OFF_STG + 2 * STG_SZ)

__device__ __forceinline__ void fa_load_kv(
    uint32_t base, const __nv_bfloat16* Kh, const __nv_bfloat16* Kl,
    const __nv_bfloat16* Vh, const __nv_bfloat16* Vl,
    int bh, int kt, int tid)
{
    const size_t gk = ((size_t)bh * SLEN + kt * 64) * QK_D;
    #pragma unroll
    for (int i = tid; i < 1024; i += 256) {
        const int r = i >> 4, c = (i & 15) * 8;
        const uint32_t so = (uint32_t)(r * QLDE + c) * 2;
        cp16(base + SOFF_KH + so, Kh + gk + (size_t)r * QK_D + c);
        cp16(base + SOFF_KL + so, Kl + gk + (size_t)r * QK_D + c);
    }
    const size_t gv = (size_t)bh * V_D * SLEN + kt * 64;
    #pragma unroll
    for (int i = tid; i < 1024; i += 256) {
        const int r = i >> 3, c = (i & 7) * 8;
        const uint32_t so = (uint32_t)(r * VLDE + c) * 2;
        cp16(base + SOFF_VH + so, Vh + gv + (size_t)r * SLEN + c);
        cp16(base + SOFF_VL + so, Vl + gv + (size_t)r * SLEN + c);
    }
}

__global__ __launch_bounds__(256, 1)
void flash_mma(const __nv_bfloat16* __restrict__ Qh, const __nv_bfloat16* __restrict__ Ql,
               const __nv_bfloat16* __restrict__ Kh, const __nv_bfloat16* __restrict__ Kl,
               const __nv_bfloat16* __restrict__ Vh, const __nv_bfloat16* __restrict__ Vl,
               __nv_bfloat16* __restrict__ Ohi, __nv_bfloat16* __restrict__ Olo)
{
    extern __shared__ char smraw[];
    const uint32_t sb0 = cvta_s(smraw);

    const int tid  = threadIdx.x;
    const int wid  = tid >> 5;
    const int lane = tid & 31;
    const int bh = blockIdx.y;
    const int b  = bh >> 4;
    const int h  = bh & 15;
    const int q0 = blockIdx.x * 128;
    const int r_base = wid * 16;

    const size_t gq = ((size_t)bh * SLEN + q0) * QK_D;
    #pragma unroll
    for (int i = tid; i < 2048; i += 256) {
        const int r = i >> 4, c = (i & 15) * 8;
        const uint32_t so = (uint32_t)(r * QLDE + c) * 2;
        cp16(sb0 + OFF_QH + so, Qh + gq + (size_t)r * QK_D + c);
        cp16(sb0 + OFF_QL + so, Ql + gq + (size_t)r * QK_D + c);
    }
    fa_load_kv(sb0 + OFF_STG, Kh, Kl, Vh, Vl, bh, 0, tid);
    cp_commit();
    asm volatile("cp.async.wait_group 0;" ::: "memory");
    __syncthreads();

    uint32_t qfh[8][4], qfl[8][4];
    {
        const int ar = lane & 15;
        const int ac = ((lane >> 4) & 1) * 8;
        #pragma unroll
        for (int kf = 0; kf < 8; ++kf) {
            const uint32_t off = (uint32_t)((r_base + ar) * QLDE + kf * 16 + ac) * 2;
            ldm_x4(qfh[kf], sb0 + OFF_QH + off);
            ldm_x4(qfl[kf], sb0 + OFF_QL + off);
        }
    }

    float Oa[16][4];
    #pragma unroll
    for (int i = 0; i < 16; ++i)
        #pragma unroll
        for (int j = 0; j < 4; ++j) Oa[i][j] = 0.f;
    float m0 = -INFINITY, m1 = -INFINITY, l0 = 0.f, l1 = 0.f;

    const int krow = lane & 7;
    const int kcol = ((lane >> 3) & 3) * 8;

    for (int kt = 0; kt < SLEN / 64; ++kt) {
        if (kt + 1 < SLEN / 64) {
            fa_load_kv(sb0 + OFF_STG + ((kt + 1) & 1) * STG_SZ,
                       Kh, Kl, Vh, Vl, bh, kt + 1, tid);
            cp_commit();
            asm volatile("cp.async.wait_group 1;" ::: "memory");
        } else {
            asm volatile("cp.async.wait_group 0;" ::: "memory");
        }
        __syncthreads();

        const uint32_t sk = sb0 + OFF_STG + (kt & 1) * STG_SZ;

        float S[8][4];
        #pragma unroll
        for (int i = 0; i < 8; ++i)
            #pragma unroll
            for (int j = 0; j < 4; ++j) S[i][j] = 0.f;

        #pragma unroll
        for (int nb = 0; nb < 8; ++nb) {
            #pragma unroll
            for (int kfp = 0; kfp < 4; ++kfp) {
                const uint32_t ko = (uint32_t)((nb * 8 + krow) * QLDE
                                               + kfp * 32 + kcol) * 2;
                uint32_t kfh[4], kfl[4];
                ldm_x4(kfh, sk + SOFF_KH + ko);
                ldm_x4(kfl, sk + SOFF_KL + ko);
                mma_bf16(S[nb], qfh[2 * kfp],     kfh);
                mma_bf16(S[nb], qfh[2 * kfp + 1], kfh + 2);
                mma_bf16(S[nb], qfl[2 * kfp],     kfh);
                mma_bf16(S[nb], qfl[2 * kfp + 1], kfh + 2);
                mma_bf16(S[nb], qfh[2 * kfp],     kfl);
                mma_bf16(S[nb], qfh[2 * kfp + 1], kfl + 2);
            }
        }

        float mx0 = -INFINITY, mx1 = -INFINITY;
        #pragma unroll
        for (int nb = 0; nb < 8; ++nb) {
            mx0 = fmaxf(mx0, fmaxf(S[nb][0], S[nb][1]));
            mx1 = fmaxf(mx1, fmaxf(S[nb][2], S[nb][3]));
        }
        mx0 = fmaxf(mx0, __shfl_xor_sync(0xffffffffu, mx0, 1));
        mx0 = fmaxf(mx0, __shfl_xor_sync(0xffffffffu, mx0, 2));
        mx1 = fmaxf(mx1, __shfl_xor_sync(0xffffffffu, mx1, 1));
        mx1 = fmaxf(mx1, __shfl_xor_sync(0xffffffffu, mx1, 2));

        const float mn0 = fmaxf(m0, mx0);
        const float mn1 = fmaxf(m1, mx1);
        const float f0 = __expf(m0 - mn0);
        const float f1 = __expf(m1 - mn1);
        m0 = mn0; m1 = mn1;

        float rs0 = 0.f, rs1 = 0.f;
        #pragma unroll
        for (int nb = 0; nb < 8; ++nb) {
            S[nb][0] = __expf(S[nb][0] - mn0);
            S[nb][1] = __expf(S[nb][1] - mn0);
            S[nb][2] = __expf(S[nb][2] - mn1);
            S[nb][3] = __expf(S[nb][3] - mn1);
            rs0 += S[nb][0] + S[nb][1];
            rs1 += S[nb][2] + S[nb][3];
        }
        rs0 += __shfl_xor_sync(0xffffffffu, rs0, 1);
        rs0 += __shfl_xor_sync(0xffffffffu, rs0, 2);
        rs1 += __shfl_xor_sync(0xffffffffu, rs1, 1);
        rs1 += __shfl_xor_sync(0xffffffffu, rs1, 2);
        l0 = l0 * f0 + rs0;
        l1 = l1 * f1 + rs1;

        #pragma unroll
        for (int i = 0; i < 16; ++i) {
            Oa[i][0] *= f0; Oa[i][1] *= f0;
            Oa[i][2] *= f1; Oa[i][3] *= f1;
        }

        uint32_t ph[4][4], pl[4][4];
        #pragma unroll
        for (int kf2 = 0; kf2 < 4; ++kf2) {
            const float* s0p = S[2 * kf2];
            const float* s1p = S[2 * kf2 + 1];
            ph[kf2][0] = pack_bf2(s0p[0], s0p[1]);
            ph[kf2][1] = pack_bf2(s0p[2], s0p[3]);
            ph[kf2][2] = pack_bf2(s1p[0], s1p[1]);
            ph[kf2][3] = pack_bf2(s1p[2], s1p[3]);
            pl[kf2][0] = pack_bf2(bf_res(s0p[0]), bf_res(s0p[1]));
            pl[kf2][1] = pack_bf2(bf_res(s0p[2]), bf_res(s0p[3]));
            pl[kf2][2] = pack_bf2(bf_res(s1p[0]), bf_res(s1p[1]));
            pl[kf2][3] = pack_bf2(bf_res(s1p[2]), bf_res(s1p[3]));
        }

        #pragma unroll
        for (int nb2 = 0; nb2 < 16; ++nb2) {
            #pragma unroll
            for (int kfp2 = 0; kfp2 < 2; ++kfp2) {
                const uint32_t vo = (uint32_t)((nb2 * 8 + krow) * VLDE
                                               + kfp2 * 32 + kcol) * 2;
                uint32_t vfh[4], vfl[4];
                ldm_x4(vfh, sk + SOFF_VH + vo);
                ldm_x4(vfl, sk + SOFF_VL + vo);
                mma_bf16(Oa[nb2], ph[2 * kfp2],     vfh);
                mma_bf16(Oa[nb2], ph[2 * kfp2 + 1], vfh + 2);
                mma_bf16(Oa[nb2], pl[2 * kfp2],     vfh);
                mma_bf16(Oa[nb2], pl[2 * kfp2 + 1], vfh + 2);
                mma_bf16(Oa[nb2], ph[2 * kfp2],     vfl);
                mma_bf16(Oa[nb2], ph[2 * kfp2 + 1], vfl + 2);
            }
        }
        __syncthreads();
    }

    const float inv0 = 1.f / l0;
    const float inv1 = 1.f / l1;
    const int er = lane >> 2;
    const int ec = (lane & 3) * 2;
    const size_t row0 = (size_t)(b * SLEN + q0 + r_base + er) * (NHEAD * V_D) + h * V_D;
    const size_t row1 = row0 + (size_t)8 * (NHEAD * V_D);
    #pragma unroll
    for (int nb2 = 0; nb2 < 16; ++nb2) {
        const int col = nb2 * 8 + ec;
        const float a0 = Oa[nb2][0] * inv0, a1 = Oa[nb2][1] * inv0;
        const float a2 = Oa[nb2][2] * inv1, a3 = Oa[nb2][3] * inv1;
        *(uint32_t*)(Ohi + row0 + col) = pack_bf2(a0, a1);
        *(uint32_t*)(Olo + row0 + col) = pack_bf2(bf_res(a0), bf_res(a1));
        *(uint32_t*)(Ohi + row1 + col) = pack_bf2(a2, a3);
        *(uint32_t*)(Olo + row1 + col) = pack_bf2(bf_res(a2), bf_res(a3));
    }
}

// ---------------------------------------------------------------------------
extern "C" void kernel_launch(void* const* d_in, const int* in_sizes, int n_in,
                              void* d_out, int out_size)
{
    const float* x    = (const float*)d_in[0];
    const float* q_a  = (const float*)d_in[1];
    const float* q_b  = (const float*)d_in[2];
    const float* kv_a = (const float*)d_in[3];
    const float* kv_b = (const float*)d_in[4];
    const float* o_w  = (const float*)d_in[5];
    float* out = (float*)d_out;

    float *XC, *Q, *KVB;
    cudaGetSymbolAddress((void**)&XC,  g_XC);
    cudaGetSymbolAddress((void**)&Q,   g_Q);
    cudaGetSymbolAddress((void**)&KVB, g_KVB);

    __nv_bfloat16 *x_hi, *x_lo, *qk_hi, *qk_lo, *qb_hi, *qb_lo;
    __nv_bfloat16 *kvb_hi, *kvb_lo, *ow_hi, *ow_lo, *XC_hi, *XC_lo;
    __nv_bfloat16 *Qb_hi, *Qb_lo, *Kb_hi, *Kb_lo, *Vt_hi, *Vt_lo, *O_hi, *O_lo;
    cudaGetSymbolAddress((void**)&x_hi,   g_x_hi);
    cudaGetSymbolAddress((void**)&x_lo,   g_x_lo);
    cudaGetSymbolAddress((void**)&qk_hi,  g_qakva_hi);
    cudaGetSymbolAddress((void**)&qk_lo,  g_qakva_lo);
    cudaGetSymbolAddress((void**)&qb_hi,  g_qb_hi);
    cudaGetSymbolAddress((void**)&qb_lo,  g_qb_lo);
    cudaGetSymbolAddress((void**)&kvb_hi, g_kvb_hi);
    cudaGetSymbolAddress((void**)&kvb_lo, g_kvb_lo);
    cudaGetSymbolAddress((void**)&ow_hi,  g_ow_hi);
    cudaGetSymbolAddress((void**)&ow_lo,  g_ow_lo);
    cudaGetSymbolAddress((void**)&XC_hi,  g_XC_hi);
    cudaGetSymbolAddress((void**)&XC_lo,  g_XC_lo);
    cudaGetSymbolAddress((void**)&Qb_hi,  g_Qb_hi);
    cudaGetSymbolAddress((void**)&Qb_lo,  g_Qb_lo);
    cudaGetSymbolAddress((void**)&Kb_hi,  g_Kb_hi);
    cudaGetSymbolAddress((void**)&Kb_lo,  g_Kb_lo);
    cudaGetSymbolAddress((void**)&Vt_hi,  g_Vt_hi);
    cudaGetSymbolAddress((void**)&Vt_lo,  g_Vt_lo);
    cudaGetSymbolAddress((void**)&O_hi,   g_O_hi);
    cudaGetSymbolAddress((void**)&O_lo,   g_O_lo);

    cudaFuncSetAttribute(gemm_one, cudaFuncAttributeMaxDynamicSharedMemorySize,
                         GEMM_SMEM);
    cudaFuncSetAttribute(gemm_two, cudaFuncAttributeMaxDynamicSharedMemorySize,
                         GEMM_SMEM);
    cudaFuncSetAttribute(flash_mma, cudaFuncAttributeMaxDynamicSharedMemorySize,
                         FLASH_SMEM);

    // 1) all input splits in one launch (q_a/kv_a land in combined buffer)
    split_all<<<SPLIT_BLOCKS, 256>>>(x, q_a, kv_a, q_b, kv_b, o_w,
                                     x_hi, x_lo, qk_hi, qk_lo,
                                     qb_hi, qb_lo, kvb_hi, kvb_lo, ow_hi, ow_lo);

    // 2) merged x-GEMM: XC = x @ [q_a; kv_a]^T  (4096 x 2112, K=2048)
    //    epilogue writes fp32 (rope slice) + bf16 hi/lo (feeds gemm2/gemm4)
    gemm_one<<<dim3(17, 32), 256, GEMM_SMEM>>>(x_hi, x_lo, EMB, qk_hi, qk_lo,
                                               XC, XC_hi, XC_lo, NXC, EMB, NXC);

    // 3) grouped: Q = Xq @ q_b^T (N=2048,K=1536)  +  KVB = ckv512 @ kv_b^T (N=3072,K=512)
    gemm_two<<<dim3(16 + 24, 32), 256, GEMM_SMEM>>>(
        XC_hi, XC_lo, NXC, qb_hi, qb_lo, Q, 2048, QRANK, 2048,
        XC_hi + QRANK, XC_lo + QRANK, NXC, kvb_hi, kvb_lo, KVB, 3072, KVRANK, 3072,
        16);

    // 4) repack (rope) to bf16 hi/lo + V transpose
    build_q<<<MROWS, dim3(64, NHEAD)>>>(Q, Qb_hi, Qb_lo);
    build_k<<<MROWS, dim3(64, NHEAD)>>>(KVB, XC, Kb_hi, Kb_lo);
    transpose_v<<<dim3(SLEN / 64, BHN), 256>>>(KVB, Vt_hi, Vt_lo);

    // 5) attention (HMMA)
    flash_mma<<<dim3(SLEN / 128, BHN), 256, FLASH_SMEM>>>(
        Qb_hi, Qb_lo, Kb_hi, Kb_lo, Vt_hi, Vt_lo, O_hi, O_lo);

    // 6) out = O @ o_w^T
    gemm_one<<<dim3(16, 32), 256, GEMM_SMEM>>>(O_hi, O_lo, EMB, ow_hi, ow_lo,
                                               out, nullptr, nullptr,
                                               EMB, NHEAD * V_D, EMB);
}